// round 8
// baseline (speedup 1.0000x reference)
#include <cuda_runtime.h>
#include <math.h>

// ---------------------------------------------------------------------------
// Problem constants
// ---------------------------------------------------------------------------
#define BATCH 4
#define SEQ   2048
#define HID   2048
#define NHEAD 16
#define HD    128
#define RNK   64
#define IDXD  512
#define NIDX  65536
#define TOPK  4
#define NTOK  512          // only first 512 tokens/batch ever attended in adapter

// ---------------------------------------------------------------------------
// Scratch (device globals; no allocation allowed)
// ---------------------------------------------------------------------------
__device__ float g_Q[(size_t)BATCH * SEQ * HID];
__device__ float g_K[(size_t)BATCH * SEQ * HID];
__device__ float g_V[(size_t)BATCH * SEQ * HID];
__device__ float g_attn[(size_t)BATCH * SEQ * HID];
__device__ float g_scores[(size_t)BATCH * NHEAD * SEQ * SEQ];   // 1.07 GB
__device__ float g_t1[(size_t)BATCH * SEQ * RNK];
__device__ float g_query[(size_t)BATCH * SEQ * IDXD];
__device__ float g_sim[(size_t)BATCH * NTOK * NIDX];            // 537 MB (fp32)
__device__ int   g_topidx[BATCH * NTOK * TOPK];
__device__ float g_aK[(size_t)BATCH * SEQ * IDXD];
__device__ float g_aV[(size_t)BATCH * SEQ * IDXD];
__device__ float g_sc2[(size_t)BATCH * SEQ * SEQ];
__device__ float g_mome[(size_t)BATCH * SEQ * IDXD];
__device__ float g_t2[(size_t)BATCH * SEQ * RNK];

// ---------------------------------------------------------------------------
// TF32 helpers (3xTF32 fp32 emulation: a = hi + lo, error ~2^-22 per product)
// ---------------------------------------------------------------------------
__device__ __forceinline__ float tf32r(float x)
{
    unsigned int u;
    asm("cvt.rna.tf32.f32 %0, %1;" : "=r"(u) : "f"(x));
    return __uint_as_float(u);
}

__device__ __forceinline__ void mma_tf32(float* c, const float* a, const float* b)
{
    asm volatile(
        "mma.sync.aligned.m16n8k8.row.col.f32.tf32.tf32.f32 "
        "{%0,%1,%2,%3}, {%4,%5,%6,%7}, {%8,%9}, {%0,%1,%2,%3};"
        : "+f"(c[0]), "+f"(c[1]), "+f"(c[2]), "+f"(c[3])
        : "r"(__float_as_uint(a[0])), "r"(__float_as_uint(a[1])),
          "r"(__float_as_uint(a[2])), "r"(__float_as_uint(a[3])),
          "r"(__float_as_uint(b[0])), "r"(__float_as_uint(b[1])));
}

// bank swizzle for the float4 k-slot index (kills store conflicts; preserves
// conflict-free fragment loads because it permutes within each 4-slot group)
__device__ __forceinline__ int swz4(int m) { return (m ^ (m >> 2)) & 3; }

#define LDA4 12          // row stride in float4 (48 words == 16 mod 32)
#define SMEM_BYTES (2 * 128 * LDA4 * 16)   // 49152 = 48 KB dynamic

// ---------------------------------------------------------------------------
// Tensor-core GEMM (3xTF32, fp32-equivalent accuracy):
//   C = alpha * A * op(B) + beta * C
//   A: [M, K] row-major. TB=true: B [N,K] -> C = A B^T; TB=false: B [K,N].
// Requirements (all call sites satisfy): M % 128 == 0, K % 16 == 0,
//   N % 8 == 0; for TB=false additionally N % 128 == 0.
// Smem layout: float4 per (row, kslot): (hi_k, lo_k, hi_{k+4}, lo_{k+4})
//   kslot = (k>=8 ? 4:0) + (k&3), half = (k>>2)&1 selects .xy/.zw.
// One LDS.128 = one complete hi+lo half-fragment.
// ---------------------------------------------------------------------------
template<bool TB>
__global__ __launch_bounds__(256)
void gemm_mma(int M, int N, int Kd, float alpha, float beta,
              const float* __restrict__ A, int lda, long sAb, long sAh,
              const float* __restrict__ B, int ldb, long sBb, long sBh,
              float* __restrict__ C, int ldc, long sCb, long sCh,
              int nh, int causal_skip, int k_limit)
{
    int z  = blockIdx.z;
    int bb = z / nh, hh = z - bb * nh;
    A += (long)bb * sAb + (long)hh * sAh;
    B += (long)bb * sBb + (long)hh * sBh;
    C += (long)bb * sCb + (long)hh * sCh;

    int row0 = blockIdx.y << 7;
    int col0 = blockIdx.x << 7;
    if (causal_skip && col0 > row0 + 127) return;

    int kEff = Kd;
    if (k_limit) { int lim = row0 + 128; if (lim < kEff) kEff = lim; }

    extern __shared__ float4 sm4[];
    float4* AT = sm4;                 // [128][LDA4]
    float4* BT = sm4 + 128 * LDA4;    // [128][LDA4]

    int tid  = threadIdx.x;
    int warp = tid >> 5, lane = tid & 31;
    int wm = warp & 1;          // m offset 0/64
    int wn = warp >> 1;         // n offset 0/32/64/96
    int grp = lane >> 2;        // 0..7
    int tig = lane & 3;         // 0..3

    float acc[16][4];
#pragma unroll
    for (int f = 0; f < 16; f++)
#pragma unroll
        for (int r = 0; r < 4; r++) acc[f][r] = 0.f;

    for (int k0 = 0; k0 < kEff; k0 += 16) {
        // ---- fill A tile: 128 rows x 16 k (2 float4 per thread) ----
#pragma unroll
        for (int s = 0; s < 2; s++) {
            int id = (tid << 1) + s;            // 0..511
            int m = id >> 2, kk = (id & 3) << 2;
            float4 v = *(const float4*)(A + (long)(row0 + m) * lda + (k0 + kk));
            int kpb  = (kk & 8) ? 4 : 0;
            int half = (kk >> 2) & 1;
            int sw = swz4(m);
            float4* rowp = AT + m * LDA4;
            float h0 = tf32r(v.x), h1 = tf32r(v.y), h2 = tf32r(v.z), h3 = tf32r(v.w);
            ((float2*)(rowp + ((kpb + 0) ^ sw)))[half] = make_float2(h0, tf32r(v.x - h0));
            ((float2*)(rowp + ((kpb + 1) ^ sw)))[half] = make_float2(h1, tf32r(v.y - h1));
            ((float2*)(rowp + ((kpb + 2) ^ sw)))[half] = make_float2(h2, tf32r(v.z - h2));
            ((float2*)(rowp + ((kpb + 3) ^ sw)))[half] = make_float2(h3, tf32r(v.w - h3));
        }
        // ---- fill B tile as BT[n][kslot] ----
        if (TB) {
#pragma unroll
            for (int s = 0; s < 2; s++) {
                int id = (tid << 1) + s;
                int n = id >> 2, kk = (id & 3) << 2;
                int gn = col0 + n;
                float4 v = make_float4(0.f, 0.f, 0.f, 0.f);
                if (gn < N) v = *(const float4*)(B + (long)gn * ldb + (k0 + kk));
                int kpb  = (kk & 8) ? 4 : 0;
                int half = (kk >> 2) & 1;
                int sw = swz4(n);
                float4* rowp = BT + n * LDA4;
                float h0 = tf32r(v.x), h1 = tf32r(v.y), h2 = tf32r(v.z), h3 = tf32r(v.w);
                ((float2*)(rowp + ((kpb + 0) ^ sw)))[half] = make_float2(h0, tf32r(v.x - h0));
                ((float2*)(rowp + ((kpb + 1) ^ sw)))[half] = make_float2(h1, tf32r(v.y - h1));
                ((float2*)(rowp + ((kpb + 2) ^ sw)))[half] = make_float2(h2, tf32r(v.z - h2));
                ((float2*)(rowp + ((kpb + 3) ^ sw)))[half] = make_float2(h3, tf32r(v.w - h3));
            }
        } else {
            // B is [K, N]; N % 128 == 0 at all TB=false call sites
#pragma unroll
            for (int s = 0; s < 8; s++) {
                int id = (s << 8) + tid;        // 0..2047
                int kk = id >> 7, n = id & 127;
                float v = B[(long)(k0 + kk) * ldb + (col0 + n)];
                int kp   = ((kk & 8) ? 4 : 0) + (kk & 3);
                int half = (kk >> 2) & 1;
                float h = tf32r(v);
                ((float2*)(BT + n * LDA4 + (kp ^ swz4(n))))[half] =
                    make_float2(h, tf32r(v - h));
            }
        }
        __syncthreads();

#pragma unroll
        for (int k8 = 0; k8 < 16; k8 += 8) {
            int kp = (k8 ? 4 : 0) + tig;

            // A fragments: 8 x LDS.128
            float ah[4][4], al[4][4];
#pragma unroll
            for (int i = 0; i < 4; i++) {
                int r = (wm << 6) + (i << 4) + grp;
                float4 f0 = AT[r * LDA4 + (kp ^ swz4(r))];
                float4 f1 = AT[(r + 8) * LDA4 + (kp ^ swz4(r + 8))];
                ah[i][0] = f0.x; al[i][0] = f0.y; ah[i][2] = f0.z; al[i][2] = f0.w;
                ah[i][1] = f1.x; al[i][1] = f1.y; ah[i][3] = f1.z; al[i][3] = f1.w;
            }
            // B fragments: 4 x LDS.128 (hoisted across all 3 passes)
            float bh[4][2], bl[4][2];
#pragma unroll
            for (int j = 0; j < 4; j++) {
                int n = (wn << 5) + (j << 3) + grp;
                float4 g = BT[n * LDA4 + (kp ^ swz4(n))];
                bh[j][0] = g.x; bl[j][0] = g.y; bh[j][1] = g.z; bl[j][1] = g.w;
            }
            // pass 0: hi*hi
#pragma unroll
            for (int j = 0; j < 4; j++)
#pragma unroll
                for (int i = 0; i < 4; i++) mma_tf32(acc[i * 4 + j], ah[i], bh[j]);
            // pass 1: hi*lo
#pragma unroll
            for (int j = 0; j < 4; j++)
#pragma unroll
                for (int i = 0; i < 4; i++) mma_tf32(acc[i * 4 + j], ah[i], bl[j]);
            // pass 2: lo*hi
#pragma unroll
            for (int j = 0; j < 4; j++)
#pragma unroll
                for (int i = 0; i < 4; i++) mma_tf32(acc[i * 4 + j], al[i], bh[j]);
        }
        __syncthreads();
    }

    // ---- epilogue ----
#pragma unroll
    for (int i = 0; i < 4; i++) {
#pragma unroll
        for (int j = 0; j < 4; j++) {
            float* c = acc[i * 4 + j];
            int gm = row0 + (wm << 6) + (i << 4) + grp;
            int gn = col0 + (wn << 5) + (j << 3) + (tig << 1);
            if (gn < N) {     // N % 8 == 0 -> gn+1 < N too
                long o0 = (long)gm * ldc + gn;
                long o1 = (long)(gm + 8) * ldc + gn;
                float2 r0, r1;
                r0.x = alpha * c[0]; r0.y = alpha * c[1];
                r1.x = alpha * c[2]; r1.y = alpha * c[3];
                if (beta != 0.f) {
                    float2 p0 = *(float2*)(C + o0);
                    float2 p1 = *(float2*)(C + o1);
                    r0.x += beta * p0.x; r0.y += beta * p0.y;
                    r1.x += beta * p1.x; r1.y += beta * p1.y;
                }
                *(float2*)(C + o0) = r0;
                *(float2*)(C + o1) = r1;
            }
        }
    }
}

// ---------------------------------------------------------------------------
// fp64-accumulated GEMM (C = A * B^T) — small t1/query chain only, so top-k
// rescoring inputs are exactly rounded.
// ---------------------------------------------------------------------------
__global__ __launch_bounds__(256)
void gemm_f64acc(int M, int N, int Kd,
                 const float* __restrict__ A, int lda, long sAb,
                 const float* __restrict__ B, int ldb,
                 float* __restrict__ C, int ldc, long sCb)
{
    int b = blockIdx.z;
    A += (long)b * sAb;
    C += (long)b * sCb;

    int row0 = blockIdx.y << 6;
    int col0 = blockIdx.x << 6;

    __shared__ float As[8][68];
    __shared__ float Bs[8][68];

    int tid = threadIdx.x;
    int tx = tid & 15, ty = tid >> 4;

    double acc[4][4];
#pragma unroll
    for (int i = 0; i < 4; i++)
#pragma unroll
        for (int j = 0; j < 4; j++) acc[i][j] = 0.0;

    for (int k0 = 0; k0 < Kd; k0 += 8) {
#pragma unroll
        for (int l = 0; l < 2; l++) {
            int idx = tid + (l << 8);
            int m = idx >> 3, k = idx & 7;
            int gm = row0 + m, gk = k0 + k;
            As[k][m] = (gm < M && gk < Kd) ? A[(long)gm * lda + gk] : 0.f;
            int gn = col0 + m;
            Bs[k][m] = (gn < N && gk < Kd) ? B[(long)gn * ldb + gk] : 0.f;
        }
        __syncthreads();

#pragma unroll
        for (int kk = 0; kk < 8; kk++) {
            float a[4], bb[4];
#pragma unroll
            for (int i = 0; i < 4; i++) a[i]  = As[kk][(ty << 2) + i];
#pragma unroll
            for (int j = 0; j < 4; j++) bb[j] = Bs[kk][(tx << 2) + j];
#pragma unroll
            for (int i = 0; i < 4; i++)
#pragma unroll
                for (int j = 0; j < 4; j++)
                    acc[i][j] = fma((double)a[i], (double)bb[j], acc[i][j]);
        }
        __syncthreads();
    }

#pragma unroll
    for (int i = 0; i < 4; i++) {
        int gm = row0 + (ty << 2) + i;
        if (gm >= M) continue;
#pragma unroll
        for (int j = 0; j < 4; j++) {
            int gn = col0 + (tx << 2) + j;
            if (gn >= N) continue;
            C[(long)gm * ldc + gn] = (float)acc[i][j];
        }
    }
}

// ---------------------------------------------------------------------------
// Causal row softmax on S[row, :T]; valid cols j <= q (q = row % L).
// ---------------------------------------------------------------------------
__global__ void causal_softmax_k(float* __restrict__ S, int L, int T)
{
    long row = blockIdx.x;
    int q = (int)(row % L);
    float* p = S + row * (long)T;
    int n = q + 1;
    int tid = threadIdx.x;
    __shared__ float red[32];

    float m = -INFINITY;
    for (int j = tid; j < n; j += blockDim.x) m = fmaxf(m, p[j]);
#pragma unroll
    for (int o = 16; o; o >>= 1) m = fmaxf(m, __shfl_xor_sync(0xffffffffu, m, o));
    if ((tid & 31) == 0) red[tid >> 5] = m;
    __syncthreads();
    if (tid < 32) {
        float v = (tid < (int)(blockDim.x >> 5)) ? red[tid] : -INFINITY;
#pragma unroll
        for (int o = 16; o; o >>= 1) v = fmaxf(v, __shfl_xor_sync(0xffffffffu, v, o));
        if (tid == 0) red[0] = v;
    }
    __syncthreads();
    m = red[0];
    __syncthreads();

    float s = 0.f;
    for (int j = tid; j < n; j += blockDim.x) {
        float e = expf(p[j] - m);
        p[j] = e;
        s += e;
    }
#pragma unroll
    for (int o = 16; o; o >>= 1) s += __shfl_xor_sync(0xffffffffu, s, o);
    if ((tid & 31) == 0) red[tid >> 5] = s;
    __syncthreads();
    if (tid < 32) {
        float v = (tid < (int)(blockDim.x >> 5)) ? red[tid] : 0.f;
#pragma unroll
        for (int o = 16; o; o >>= 1) v += __shfl_xor_sync(0xffffffffu, v, o);
        if (tid == 0) red[0] = v;
    }
    __syncthreads();
    float inv = 1.f / red[0];
    for (int j = tid; j < n; j += blockDim.x) p[j] *= inv;
    for (int j = n + tid; j < T; j += blockDim.x) p[j] = 0.f;
}

// ---------------------------------------------------------------------------
// Top-4 with fp64 refinement (phases: stripe top-4 -> serial top-16 ->
// fp64 rescore -> top-4). Tie-break: lower index (matches jax.lax.top_k).
// ---------------------------------------------------------------------------
__global__ __launch_bounds__(256)
void topk4_refine_k(const float* __restrict__ sim,
                    const float* __restrict__ qry,
                    const float* __restrict__ keys,
                    int* __restrict__ out)
{
    long row = blockIdx.x;
    int b   = (int)(row >> 9);
    int tok = (int)(row & (NTOK - 1));
    const float* p = sim + row * (long)NIDX;
    int tid = threadIdx.x;

    float v0 = -INFINITY, v1 = -INFINITY, v2 = -INFINITY, v3 = -INFINITY;
    int   i0 = 0x7fffffff, i1 = 0x7fffffff, i2 = 0x7fffffff, i3 = 0x7fffffff;

    for (int j = tid; j < NIDX; j += 256) {
        float x = p[j];
        if (x > v3 || (x == v3 && j < i3)) {
            if (x > v0 || (x == v0 && j < i0)) {
                v3 = v2; i3 = i2; v2 = v1; i2 = i1; v1 = v0; i1 = i0; v0 = x; i0 = j;
            } else if (x > v1 || (x == v1 && j < i1)) {
                v3 = v2; i3 = i2; v2 = v1; i2 = i1; v1 = x; i1 = j;
            } else if (x > v2 || (x == v2 && j < i2)) {
                v3 = v2; i3 = i2; v2 = x; i2 = j;
            } else {
                v3 = x; i3 = j;
            }
        }
    }

    __shared__ float sv[1024];
    __shared__ int   si[1024];
    sv[tid * 4 + 0] = v0; si[tid * 4 + 0] = i0;
    sv[tid * 4 + 1] = v1; si[tid * 4 + 1] = i1;
    sv[tid * 4 + 2] = v2; si[tid * 4 + 2] = i2;
    sv[tid * 4 + 3] = v3; si[tid * 4 + 3] = i3;
    __syncthreads();

    __shared__ int   cidx[16];
    __shared__ float cval[16];
    if (tid == 0) {
        for (int r = 0; r < 16; r++) {
            float best = -INFINITY; int bid = 0x7fffffff; int bp = -1;
            for (int i = 0; i < 1024; i++) {
                float x = sv[i];
                if (x > best || (x == best && si[i] < bid)) { best = x; bid = si[i]; bp = i; }
            }
            cidx[r] = bid;
            sv[bp] = -INFINITY; si[bp] = 0x7fffffff;
        }
    }
    __syncthreads();

    {
        int warp = tid >> 5, lane = tid & 31;
        int c = (warp << 1) + (lane >> 4);
        int l = lane & 15;
        const float* qrow = qry + ((long)b * SEQ + tok) * IDXD;
        const float* krow = keys + (long)cidx[c] * IDXD;
        double s = 0.0;
        for (int t = l; t < IDXD; t += 16)
            s = fma((double)qrow[t], (double)krow[t], s);
#pragma unroll
        for (int o = 8; o; o >>= 1) s += __shfl_xor_sync(0xffffffffu, s, o, 16);
        if (l == 0) cval[c] = (float)s;
    }
    __syncthreads();

    if (tid == 0) {
        float lv[16]; int li[16];
#pragma unroll
        for (int i = 0; i < 16; i++) { lv[i] = cval[i]; li[i] = cidx[i]; }
        for (int r = 0; r < TOPK; r++) {
            float best = -INFINITY; int bid = 0x7fffffff; int bp = -1;
#pragma unroll
            for (int i = 0; i < 16; i++) {
                float x = lv[i];
                if (x > best || (x == best && li[i] < bid)) { best = x; bid = li[i]; bp = i; }
            }
            out[row * TOPK + r] = bid;
            lv[bp] = -INFINITY; li[bp] = 0x7fffffff;
        }
    }
}

// ---------------------------------------------------------------------------
// Gather adapter K/V rows
// ---------------------------------------------------------------------------
__global__ void gather_k(const int* __restrict__ tidx,
                         const float* __restrict__ keys,
                         const float* __restrict__ vals,
                         float* __restrict__ aK, float* __restrict__ aV)
{
    int blk = blockIdx.x;
    int b = blk >> 11;
    int j = blk & 2047;
    int id = tidx[((b * NTOK + (j >> 2)) << 2) + (j & 3)];
    const float4* ks = (const float4*)(keys + (long)id * IDXD);
    const float4* vs = (const float4*)(vals + (long)id * IDXD);
    float4* dk = (float4*)(aK + (long)blk * IDXD);
    float4* dv = (float4*)(aV + (long)blk * IDXD);
    int t = threadIdx.x;
    dk[t] = ks[t];
    dv[t] = vs[t];
}

// ---------------------------------------------------------------------------
// Host launch
// ---------------------------------------------------------------------------
extern "C" void kernel_launch(void* const* d_in, const int* in_sizes, int n_in,
                              void* d_out, int out_size)
{
    const float* hs    = (const float*)d_in[0];
    const float* Wq    = (const float*)d_in[1];
    const float* Wk    = (const float*)d_in[2];
    const float* Wv    = (const float*)d_in[3];
    const float* Wo    = (const float*)d_in[4];
    const float* q_in  = (const float*)d_in[5];
    const float* q_out = (const float*)d_in[6];
    const float* v_in  = (const float*)d_in[7];
    const float* v_out = (const float*)d_in[8];
    const float* ikeys = (const float*)d_in[9];
    const float* ivals = (const float*)d_in[10];
    float* out = (float*)d_out;

    void* p;
    cudaGetSymbolAddress(&p, g_Q);      float* Qb   = (float*)p;
    cudaGetSymbolAddress(&p, g_K);      float* Kb   = (float*)p;
    cudaGetSymbolAddress(&p, g_V);      float* Vb   = (float*)p;
    cudaGetSymbolAddress(&p, g_attn);   float* Ab   = (float*)p;
    cudaGetSymbolAddress(&p, g_scores); float* Sb   = (float*)p;
    cudaGetSymbolAddress(&p, g_t1);     float* t1   = (float*)p;
    cudaGetSymbolAddress(&p, g_query);  float* qry  = (float*)p;
    cudaGetSymbolAddress(&p, g_sim);    float* simb = (float*)p;
    cudaGetSymbolAddress(&p, g_topidx); int*   topi = (int*)p;
    cudaGetSymbolAddress(&p, g_aK);     float* aK   = (float*)p;
    cudaGetSymbolAddress(&p, g_aV);     float* aV   = (float*)p;
    cudaGetSymbolAddress(&p, g_sc2);    float* sc2  = (float*)p;
    cudaGetSymbolAddress(&p, g_mome);   float* mome = (float*)p;
    cudaGetSymbolAddress(&p, g_t2);     float* t2   = (float*)p;

    const int MS = BATCH * SEQ;                        // 8192
    const float scale_base = 1.0f / sqrtf((float)HD);
    const float scale_adpt = 1.0f / sqrtf((float)IDXD);
    dim3 blk(256);
    const int SB = SMEM_BYTES;   // 49152 (== default 48KB dynamic smem cap)

    // 1) Q/K/V projections: [8192,2048] = hs @ W^T
    gemm_mma<true><<<dim3(HID / 128, MS / 128, 1), blk, SB>>>(MS, HID, HID, 1.f, 0.f,
        hs, HID, 0, 0, Wq, HID, 0, 0, Qb, HID, 0, 0, 1, 0, 0);
    gemm_mma<true><<<dim3(HID / 128, MS / 128, 1), blk, SB>>>(MS, HID, HID, 1.f, 0.f,
        hs, HID, 0, 0, Wk, HID, 0, 0, Kb, HID, 0, 0, 1, 0, 0);
    gemm_mma<true><<<dim3(HID / 128, MS / 128, 1), blk, SB>>>(MS, HID, HID, 1.f, 0.f,
        hs, HID, 0, 0, Wv, HID, 0, 0, Vb, HID, 0, 0, 1, 0, 0);

    // 2) base scores (batched over b,h), causal tile-skip
    gemm_mma<true><<<dim3(SEQ / 128, SEQ / 128, BATCH * NHEAD), blk, SB>>>(
        SEQ, SEQ, HD, scale_base, 0.f,
        Qb, HID, (long)SEQ * HID, HD,
        Kb, HID, (long)SEQ * HID, HD,
        Sb, SEQ, (long)NHEAD * SEQ * SEQ, (long)SEQ * SEQ,
        NHEAD, 1, 0);

    // 3) causal softmax
    causal_softmax_k<<<BATCH * NHEAD * SEQ, 256>>>(Sb, SEQ, SEQ);

    // 4) AV: attn_out = P @ V (NN, causal K-limit)
    gemm_mma<false><<<dim3(1, SEQ / 128, BATCH * NHEAD), blk, SB>>>(
        SEQ, HD, SEQ, 1.f, 0.f,
        Sb, SEQ, (long)NHEAD * SEQ * SEQ, (long)SEQ * SEQ,
        Vb, HID, (long)SEQ * HID, HD,
        Ab, HID, (long)SEQ * HID, HD,
        NHEAD, 0, 1);

    // 5) out = attn_out @ Wo^T
    gemm_mma<true><<<dim3(HID / 128, MS / 128, 1), blk, SB>>>(MS, HID, HID, 1.f, 0.f,
        Ab, HID, 0, 0, Wo, HID, 0, 0, out, HID, 0, 0, 1, 0, 0);

    // 6) t1 = hs @ q_in^T   [8192,64]  (fp64: feeds top-k chain)
    gemm_f64acc<<<dim3(RNK / 64, MS / 64, 1), blk>>>(MS, RNK, HID,
        hs, HID, 0, q_in, HID, t1, RNK, 0);

    // 7) query = t1 @ q_out^T   [8192,512]  (fp64)
    gemm_f64acc<<<dim3(IDXD / 64, MS / 64, 1), blk>>>(MS, IDXD, RNK,
        t1, RNK, 0, q_out, RNK, qry, IDXD, 0);

    // 8) sim = query[:512 tokens/batch] @ index_keys^T  (3xTF32, batched)
    gemm_mma<true><<<dim3(NIDX / 128, NTOK / 128, BATCH), blk, SB>>>(
        NTOK, NIDX, IDXD, 1.f, 0.f,
        qry, IDXD, (long)SEQ * IDXD, 0,
        ikeys, IDXD, 0, 0,
        simb, NIDX, (long)NTOK * NIDX, 0,
        1, 0, 0);

    // 9) top-4 per row with fp64 candidate rescoring
    topk4_refine_k<<<BATCH * NTOK, 256>>>(simb, qry, ikeys, topi);

    // 10) gather adapter K/V
    gather_k<<<BATCH * SEQ, 128>>>(topi, ikeys, ivals, aK, aV);

    // 11) adapter scores = query @ aK^T (batched over b, causal tile-skip)
    gemm_mma<true><<<dim3(SEQ / 128, SEQ / 128, BATCH), blk, SB>>>(
        SEQ, SEQ, IDXD, scale_adpt, 0.f,
        qry, IDXD, (long)SEQ * IDXD, 0,
        aK, IDXD, (long)SEQ * IDXD, 0,
        sc2, SEQ, (long)SEQ * SEQ, 0,
        1, 1, 0);

    // 12) causal softmax
    causal_softmax_k<<<BATCH * SEQ, 256>>>(sc2, SEQ, SEQ);

    // 13) mome_attn = P @ aV (NN, causal K-limit)
    gemm_mma<false><<<dim3(IDXD / 128, SEQ / 128, BATCH), blk, SB>>>(
        SEQ, IDXD, SEQ, 1.f, 0.f,
        sc2, SEQ, (long)SEQ * SEQ, 0,
        aV, IDXD, (long)SEQ * IDXD, 0,
        mome, IDXD, (long)SEQ * IDXD, 0,
        1, 0, 1);

    // 14) t2 = mome @ v_in^T   [8192,64]
    gemm_mma<true><<<dim3(1, MS / 128, 1), blk, SB>>>(MS, RNK, IDXD, 1.f, 0.f,
        mome, IDXD, 0, 0, v_in, IDXD, 0, 0, t2, RNK, 0, 0, 1, 0, 0);

    // 15) out += R * (t2 @ v_out^T)
    gemm_mma<true><<<dim3(HID / 128, MS / 128, 1), blk, SB>>>(MS, HID, RNK,
        (float)RNK, 1.f,
        t2, RNK, 0, 0, v_out, RNK, 0, 0, out, HID, 0, 0, 1, 0, 0);
}

// round 11
// speedup vs baseline: 1.1152x; 1.1152x over previous
#include <cuda_runtime.h>
#include <math.h>

// ---------------------------------------------------------------------------
// Problem constants
// ---------------------------------------------------------------------------
#define BATCH 4
#define SEQ   2048
#define HID   2048
#define NHEAD 16
#define HD    128
#define RNK   64
#define IDXD  512
#define NIDX  65536
#define TOPK  4
#define NTOK  512          // only first 512 tokens/batch ever attended in adapter

// ---------------------------------------------------------------------------
// Scratch (device globals; no allocation allowed)
// ---------------------------------------------------------------------------
__device__ float g_Q[(size_t)BATCH * SEQ * HID];
__device__ float g_K[(size_t)BATCH * SEQ * HID];
__device__ float g_V[(size_t)BATCH * SEQ * HID];
__device__ float g_attn[(size_t)BATCH * SEQ * HID];
__device__ float g_scores[(size_t)BATCH * NHEAD * SEQ * SEQ];   // 1.07 GB
__device__ float g_t1[(size_t)BATCH * SEQ * RNK];
__device__ float g_query[(size_t)BATCH * SEQ * IDXD];
__device__ float g_sim[(size_t)BATCH * NTOK * NIDX];            // 537 MB (fp32)
__device__ int   g_topidx[BATCH * NTOK * TOPK];
__device__ float g_aK[(size_t)BATCH * SEQ * IDXD];
__device__ float g_aV[(size_t)BATCH * SEQ * IDXD];
__device__ float g_sc2[(size_t)BATCH * SEQ * SEQ];
__device__ float g_mome[(size_t)BATCH * SEQ * IDXD];
__device__ float g_t2[(size_t)BATCH * SEQ * RNK];

// ---------------------------------------------------------------------------
// TF32 helpers (3xTF32 fp32 emulation: a = hi + lo, error ~2^-22 per product)
// ---------------------------------------------------------------------------
__device__ __forceinline__ float tf32r(float x)
{
    unsigned int u;
    asm("cvt.rna.tf32.f32 %0, %1;" : "=r"(u) : "f"(x));
    return __uint_as_float(u);
}

__device__ __forceinline__ void mma_tf32(float* c, const float* a, const float* b)
{
    asm volatile(
        "mma.sync.aligned.m16n8k8.row.col.f32.tf32.tf32.f32 "
        "{%0,%1,%2,%3}, {%4,%5,%6,%7}, {%8,%9}, {%0,%1,%2,%3};"
        : "+f"(c[0]), "+f"(c[1]), "+f"(c[2]), "+f"(c[3])
        : "r"(__float_as_uint(a[0])), "r"(__float_as_uint(a[1])),
          "r"(__float_as_uint(a[2])), "r"(__float_as_uint(a[3])),
          "r"(__float_as_uint(b[0])), "r"(__float_as_uint(b[1])));
}

// bank swizzle for the float4 k-slot index (kills store conflicts; preserves
// conflict-free fragment loads because it permutes within each 4-slot group)
__device__ __forceinline__ int swz4(int m) { return (m ^ (m >> 2)) & 3; }

#define LDA4 12          // row stride in float4 (48 words == 16 mod 32)
#define SMEM_BYTES (2 * 128 * LDA4 * 16)   // 49152 = 48 KB dynamic

// ---------------------------------------------------------------------------
// Tensor-core GEMM (3xTF32, fp32-equivalent accuracy):
//   C = alpha * A * op(B) + beta * C
//   A: [M, K] row-major. TB=true: B [N,K] -> C = A B^T; TB=false: B [K,N].
// Requirements (all call sites satisfy): M % 128 == 0, K % 16 == 0,
//   N % 8 == 0; for TB=false additionally N % 128 == 0.
// Smem: float4 per (row, kslot) = (hi_k, lo_k, hi_{k+4}, lo_{k+4});
// fragment loads are single LDS.128; all swizzled addresses hoisted out of
// the k-loop (kp^sw == (k8?4:0) + (tig^sw) since bit2 is swizzle-invariant).
// 2 CTAs/SM enforced for latency hiding (<=128 regs).
// ---------------------------------------------------------------------------
template<bool TB>
__global__ __launch_bounds__(256, 2)
void gemm_mma(int M, int N, int Kd, float alpha, float beta,
              const float* __restrict__ A, int lda, long sAb, long sAh,
              const float* __restrict__ B, int ldb, long sBb, long sBh,
              float* __restrict__ C, int ldc, long sCb, long sCh,
              int nh, int causal_skip, int k_limit)
{
    int z  = blockIdx.z;
    int bb = z / nh, hh = z - bb * nh;
    A += (long)bb * sAb + (long)hh * sAh;
    B += (long)bb * sBb + (long)hh * sBh;
    C += (long)bb * sCb + (long)hh * sCh;

    int row0 = blockIdx.y << 7;
    int col0 = blockIdx.x << 7;
    if (causal_skip && col0 > row0 + 127) return;

    int kEff = Kd;
    if (k_limit) { int lim = row0 + 128; if (lim < kEff) kEff = lim; }

    extern __shared__ float4 sm4[];
    float4* AT = sm4;                 // [128][LDA4]
    float4* BT = sm4 + 128 * LDA4;    // [128][LDA4]

    int tid  = threadIdx.x;
    int warp = tid >> 5, lane = tid & 31;
    int wm = warp & 1;          // m offset 0/64
    int wn = warp >> 1;         // n offset 0/32/64/96
    int grp = lane >> 2;        // 0..7
    int tig = lane & 3;         // 0..3

    // ---- hoisted fragment addresses (k8 adds +4) ----
    int abase[4][2], bbase[4];
#pragma unroll
    for (int i = 0; i < 4; i++) {
        int r = (wm << 6) + (i << 4) + grp;
        abase[i][0] = r * LDA4 + (tig ^ swz4(r));
        abase[i][1] = (r + 8) * LDA4 + (tig ^ swz4(r + 8));
    }
#pragma unroll
    for (int j = 0; j < 4; j++) {
        int n = (wn << 5) + (j << 3) + grp;
        bbase[j] = n * LDA4 + (tig ^ swz4(n));
    }
    // ---- hoisted store-side addresses ----
    int a_st[2], b_st[2];   // float2 slot index within row-pair layout
    {
#pragma unroll
        for (int s = 0; s < 2; s++) {
            int id = (tid << 1) + s;
            int m = id >> 2, kk = (id & 3) << 2;
            int kpb = (kk & 8) ? 4 : 0;
            a_st[s] = m * LDA4 + (kpb ^ swz4(m));   // base float4 slot; +1..+3 via ^? no:
        }
    }

    float acc[16][4];
#pragma unroll
    for (int f = 0; f < 16; f++)
#pragma unroll
        for (int r = 0; r < 4; r++) acc[f][r] = 0.f;

    for (int k0 = 0; k0 < kEff; k0 += 16) {
        // ---- fill A tile: 128 rows x 16 k (2 float4 per thread) ----
#pragma unroll
        for (int s = 0; s < 2; s++) {
            int id = (tid << 1) + s;            // 0..511
            int m = id >> 2, kk = (id & 3) << 2;
            float4 v = *(const float4*)(A + (long)(row0 + m) * lda + (k0 + kk));
            int kpb  = (kk & 8) ? 4 : 0;
            int half = (kk >> 2) & 1;
            int sw = swz4(m);
            float4* rowp = AT + m * LDA4;
            float h0 = tf32r(v.x), h1 = tf32r(v.y), h2 = tf32r(v.z), h3 = tf32r(v.w);
            ((float2*)(rowp + ((kpb + 0) ^ sw)))[half] = make_float2(h0, tf32r(v.x - h0));
            ((float2*)(rowp + ((kpb + 1) ^ sw)))[half] = make_float2(h1, tf32r(v.y - h1));
            ((float2*)(rowp + ((kpb + 2) ^ sw)))[half] = make_float2(h2, tf32r(v.z - h2));
            ((float2*)(rowp + ((kpb + 3) ^ sw)))[half] = make_float2(h3, tf32r(v.w - h3));
        }
        // ---- fill B tile as BT[n][kslot] ----
        if (TB) {
#pragma unroll
            for (int s = 0; s < 2; s++) {
                int id = (tid << 1) + s;
                int n = id >> 2, kk = (id & 3) << 2;
                int gn = col0 + n;
                float4 v = make_float4(0.f, 0.f, 0.f, 0.f);
                if (gn < N) v = *(const float4*)(B + (long)gn * ldb + (k0 + kk));
                int kpb  = (kk & 8) ? 4 : 0;
                int half = (kk >> 2) & 1;
                int sw = swz4(n);
                float4* rowp = BT + n * LDA4;
                float h0 = tf32r(v.x), h1 = tf32r(v.y), h2 = tf32r(v.z), h3 = tf32r(v.w);
                ((float2*)(rowp + ((kpb + 0) ^ sw)))[half] = make_float2(h0, tf32r(v.x - h0));
                ((float2*)(rowp + ((kpb + 1) ^ sw)))[half] = make_float2(h1, tf32r(v.y - h1));
                ((float2*)(rowp + ((kpb + 2) ^ sw)))[half] = make_float2(h2, tf32r(v.z - h2));
                ((float2*)(rowp + ((kpb + 3) ^ sw)))[half] = make_float2(h3, tf32r(v.w - h3));
            }
        } else {
            // B is [K, N]; N % 128 == 0 at all TB=false call sites
#pragma unroll
            for (int s = 0; s < 8; s++) {
                int id = (s << 8) + tid;        // 0..2047
                int kk = id >> 7, n = id & 127;
                float v = B[(long)(k0 + kk) * ldb + (col0 + n)];
                int kp   = ((kk & 8) ? 4 : 0) + (kk & 3);
                int half = (kk >> 2) & 1;
                float h = tf32r(v);
                ((float2*)(BT + n * LDA4 + (kp ^ swz4(n))))[half] =
                    make_float2(h, tf32r(v - h));
            }
        }
        __syncthreads();

#pragma unroll
        for (int k8 = 0; k8 < 2; k8++) {
            int ko = k8 ? 4 : 0;

            // A fragments: 8 x LDS.128 (addresses precomputed)
            float ah[4][4], al[4][4];
#pragma unroll
            for (int i = 0; i < 4; i++) {
                float4 f0 = AT[abase[i][0] + ko];
                float4 f1 = AT[abase[i][1] + ko];
                ah[i][0] = f0.x; al[i][0] = f0.y; ah[i][2] = f0.z; al[i][2] = f0.w;
                ah[i][1] = f1.x; al[i][1] = f1.y; ah[i][3] = f1.z; al[i][3] = f1.w;
            }
            // B fragments: 4 x LDS.128 (hoisted across all 3 passes)
            float bh[4][2], bl[4][2];
#pragma unroll
            for (int j = 0; j < 4; j++) {
                float4 g = BT[bbase[j] + ko];
                bh[j][0] = g.x; bl[j][0] = g.y; bh[j][1] = g.z; bl[j][1] = g.w;
            }
            // pass 0: hi*hi
#pragma unroll
            for (int j = 0; j < 4; j++)
#pragma unroll
                for (int i = 0; i < 4; i++) mma_tf32(acc[i * 4 + j], ah[i], bh[j]);
            // pass 1: hi*lo
#pragma unroll
            for (int j = 0; j < 4; j++)
#pragma unroll
                for (int i = 0; i < 4; i++) mma_tf32(acc[i * 4 + j], ah[i], bl[j]);
            // pass 2: lo*hi
#pragma unroll
            for (int j = 0; j < 4; j++)
#pragma unroll
                for (int i = 0; i < 4; i++) mma_tf32(acc[i * 4 + j], al[i], bh[j]);
        }
        __syncthreads();
    }

    // ---- epilogue ----
#pragma unroll
    for (int i = 0; i < 4; i++) {
#pragma unroll
        for (int j = 0; j < 4; j++) {
            float* c = acc[i * 4 + j];
            int gm = row0 + (wm << 6) + (i << 4) + grp;
            int gn = col0 + (wn << 5) + (j << 3) + (tig << 1);
            if (gn < N) {     // N % 8 == 0 -> gn+1 < N too
                long o0 = (long)gm * ldc + gn;
                long o1 = (long)(gm + 8) * ldc + gn;
                float2 r0, r1;
                r0.x = alpha * c[0]; r0.y = alpha * c[1];
                r1.x = alpha * c[2]; r1.y = alpha * c[3];
                if (beta != 0.f) {
                    float2 p0 = *(float2*)(C + o0);
                    float2 p1 = *(float2*)(C + o1);
                    r0.x += beta * p0.x; r0.y += beta * p0.y;
                    r1.x += beta * p1.x; r1.y += beta * p1.y;
                }
                *(float2*)(C + o0) = r0;
                *(float2*)(C + o1) = r1;
            }
        }
    }
}

// ---------------------------------------------------------------------------
// fp64-accumulated GEMM (C = A * B^T) — small t1/query chain only, so top-k
// rescoring inputs are exactly rounded.
// ---------------------------------------------------------------------------
__global__ __launch_bounds__(256)
void gemm_f64acc(int M, int N, int Kd,
                 const float* __restrict__ A, int lda, long sAb,
                 const float* __restrict__ B, int ldb,
                 float* __restrict__ C, int ldc, long sCb)
{
    int b = blockIdx.z;
    A += (long)b * sAb;
    C += (long)b * sCb;

    int row0 = blockIdx.y << 6;
    int col0 = blockIdx.x << 6;

    __shared__ float As[8][68];
    __shared__ float Bs[8][68];

    int tid = threadIdx.x;
    int tx = tid & 15, ty = tid >> 4;

    double acc[4][4];
#pragma unroll
    for (int i = 0; i < 4; i++)
#pragma unroll
        for (int j = 0; j < 4; j++) acc[i][j] = 0.0;

    for (int k0 = 0; k0 < Kd; k0 += 8) {
#pragma unroll
        for (int l = 0; l < 2; l++) {
            int idx = tid + (l << 8);
            int m = idx >> 3, k = idx & 7;
            int gm = row0 + m, gk = k0 + k;
            As[k][m] = (gm < M && gk < Kd) ? A[(long)gm * lda + gk] : 0.f;
            int gn = col0 + m;
            Bs[k][m] = (gn < N && gk < Kd) ? B[(long)gn * ldb + gk] : 0.f;
        }
        __syncthreads();

#pragma unroll
        for (int kk = 0; kk < 8; kk++) {
            float a[4], bb[4];
#pragma unroll
            for (int i = 0; i < 4; i++) a[i]  = As[kk][(ty << 2) + i];
#pragma unroll
            for (int j = 0; j < 4; j++) bb[j] = Bs[kk][(tx << 2) + j];
#pragma unroll
            for (int i = 0; i < 4; i++)
#pragma unroll
                for (int j = 0; j < 4; j++)
                    acc[i][j] = fma((double)a[i], (double)bb[j], acc[i][j]);
        }
        __syncthreads();
    }

#pragma unroll
    for (int i = 0; i < 4; i++) {
        int gm = row0 + (ty << 2) + i;
        if (gm >= M) continue;
#pragma unroll
        for (int j = 0; j < 4; j++) {
            int gn = col0 + (tx << 2) + j;
            if (gn >= N) continue;
            C[(long)gm * ldc + gn] = (float)acc[i][j];
        }
    }
}

// ---------------------------------------------------------------------------
// Causal row softmax on S[row, :T]; valid cols j <= q (q = row % L).
// ---------------------------------------------------------------------------
__global__ void causal_softmax_k(float* __restrict__ S, int L, int T)
{
    long row = blockIdx.x;
    int q = (int)(row % L);
    float* p = S + row * (long)T;
    int n = q + 1;
    int tid = threadIdx.x;
    __shared__ float red[32];

    float m = -INFINITY;
    for (int j = tid; j < n; j += blockDim.x) m = fmaxf(m, p[j]);
#pragma unroll
    for (int o = 16; o; o >>= 1) m = fmaxf(m, __shfl_xor_sync(0xffffffffu, m, o));
    if ((tid & 31) == 0) red[tid >> 5] = m;
    __syncthreads();
    if (tid < 32) {
        float v = (tid < (int)(blockDim.x >> 5)) ? red[tid] : -INFINITY;
#pragma unroll
        for (int o = 16; o; o >>= 1) v = fmaxf(v, __shfl_xor_sync(0xffffffffu, v, o));
        if (tid == 0) red[0] = v;
    }
    __syncthreads();
    m = red[0];
    __syncthreads();

    float s = 0.f;
    for (int j = tid; j < n; j += blockDim.x) {
        float e = expf(p[j] - m);
        p[j] = e;
        s += e;
    }
#pragma unroll
    for (int o = 16; o; o >>= 1) s += __shfl_xor_sync(0xffffffffu, s, o);
    if ((tid & 31) == 0) red[tid >> 5] = s;
    __syncthreads();
    if (tid < 32) {
        float v = (tid < (int)(blockDim.x >> 5)) ? red[tid] : 0.f;
#pragma unroll
        for (int o = 16; o; o >>= 1) v += __shfl_xor_sync(0xffffffffu, v, o);
        if (tid == 0) red[0] = v;
    }
    __syncthreads();
    float inv = 1.f / red[0];
    for (int j = tid; j < n; j += blockDim.x) p[j] *= inv;
    for (int j = n + tid; j < T; j += blockDim.x) p[j] = 0.f;
}

// ---------------------------------------------------------------------------
// Top-4 with fp64 refinement (phases: stripe top-4 -> serial top-16 ->
// fp64 rescore -> top-4). Tie-break: lower index (matches jax.lax.top_k).
// ---------------------------------------------------------------------------
__global__ __launch_bounds__(256)
void topk4_refine_k(const float* __restrict__ sim,
                    const float* __restrict__ qry,
                    const float* __restrict__ keys,
                    int* __restrict__ out)
{
    long row = blockIdx.x;
    int b   = (int)(row >> 9);
    int tok = (int)(row & (NTOK - 1));
    const float* p = sim + row * (long)NIDX;
    int tid = threadIdx.x;

    float v0 = -INFINITY, v1 = -INFINITY, v2 = -INFINITY, v3 = -INFINITY;
    int   i0 = 0x7fffffff, i1 = 0x7fffffff, i2 = 0x7fffffff, i3 = 0x7fffffff;

    for (int j = tid; j < NIDX; j += 256) {
        float x = p[j];
        if (x > v3 || (x == v3 && j < i3)) {
            if (x > v0 || (x == v0 && j < i0)) {
                v3 = v2; i3 = i2; v2 = v1; i2 = i1; v1 = v0; i1 = i0; v0 = x; i0 = j;
            } else if (x > v1 || (x == v1 && j < i1)) {
                v3 = v2; i3 = i2; v2 = v1; i2 = i1; v1 = x; i1 = j;
            } else if (x > v2 || (x == v2 && j < i2)) {
                v3 = v2; i3 = i2; v2 = x; i2 = j;
            } else {
                v3 = x; i3 = j;
            }
        }
    }

    __shared__ float sv[1024];
    __shared__ int   si[1024];
    sv[tid * 4 + 0] = v0; si[tid * 4 + 0] = i0;
    sv[tid * 4 + 1] = v1; si[tid * 4 + 1] = i1;
    sv[tid * 4 + 2] = v2; si[tid * 4 + 2] = i2;
    sv[tid * 4 + 3] = v3; si[tid * 4 + 3] = i3;
    __syncthreads();

    __shared__ int   cidx[16];
    __shared__ float cval[16];
    if (tid == 0) {
        for (int r = 0; r < 16; r++) {
            float best = -INFINITY; int bid = 0x7fffffff; int bp = -1;
            for (int i = 0; i < 1024; i++) {
                float x = sv[i];
                if (x > best || (x == best && si[i] < bid)) { best = x; bid = si[i]; bp = i; }
            }
            cidx[r] = bid;
            sv[bp] = -INFINITY; si[bp] = 0x7fffffff;
        }
    }
    __syncthreads();

    {
        int warp = tid >> 5, lane = tid & 31;
        int c = (warp << 1) + (lane >> 4);
        int l = lane & 15;
        const float* qrow = qry + ((long)b * SEQ + tok) * IDXD;
        const float* krow = keys + (long)cidx[c] * IDXD;
        double s = 0.0;
        for (int t = l; t < IDXD; t += 16)
            s = fma((double)qrow[t], (double)krow[t], s);
#pragma unroll
        for (int o = 8; o; o >>= 1) s += __shfl_xor_sync(0xffffffffu, s, o, 16);
        if (l == 0) cval[c] = (float)s;
    }
    __syncthreads();

    if (tid == 0) {
        float lv[16]; int li[16];
#pragma unroll
        for (int i = 0; i < 16; i++) { lv[i] = cval[i]; li[i] = cidx[i]; }
        for (int r = 0; r < TOPK; r++) {
            float best = -INFINITY; int bid = 0x7fffffff; int bp = -1;
#pragma unroll
            for (int i = 0; i < 16; i++) {
                float x = lv[i];
                if (x > best || (x == best && li[i] < bid)) { best = x; bid = li[i]; bp = i; }
            }
            out[row * TOPK + r] = bid;
            lv[bp] = -INFINITY; li[bp] = 0x7fffffff;
        }
    }
}

// ---------------------------------------------------------------------------
// Gather adapter K/V rows
// ---------------------------------------------------------------------------
__global__ void gather_k(const int* __restrict__ tidx,
                         const float* __restrict__ keys,
                         const float* __restrict__ vals,
                         float* __restrict__ aK, float* __restrict__ aV)
{
    int blk = blockIdx.x;
    int b = blk >> 11;
    int j = blk & 2047;
    int id = tidx[((b * NTOK + (j >> 2)) << 2) + (j & 3)];
    const float4* ks = (const float4*)(keys + (long)id * IDXD);
    const float4* vs = (const float4*)(vals + (long)id * IDXD);
    float4* dk = (float4*)(aK + (long)blk * IDXD);
    float4* dv = (float4*)(aV + (long)blk * IDXD);
    int t = threadIdx.x;
    dk[t] = ks[t];
    dv[t] = vs[t];
}

// ---------------------------------------------------------------------------
// Host launch
// ---------------------------------------------------------------------------
extern "C" void kernel_launch(void* const* d_in, const int* in_sizes, int n_in,
                              void* d_out, int out_size)
{
    const float* hs    = (const float*)d_in[0];
    const float* Wq    = (const float*)d_in[1];
    const float* Wk    = (const float*)d_in[2];
    const float* Wv    = (const float*)d_in[3];
    const float* Wo    = (const float*)d_in[4];
    const float* q_in  = (const float*)d_in[5];
    const float* q_out = (const float*)d_in[6];
    const float* v_in  = (const float*)d_in[7];
    const float* v_out = (const float*)d_in[8];
    const float* ikeys = (const float*)d_in[9];
    const float* ivals = (const float*)d_in[10];
    float* out = (float*)d_out;

    void* p;
    cudaGetSymbolAddress(&p, g_Q);      float* Qb   = (float*)p;
    cudaGetSymbolAddress(&p, g_K);      float* Kb   = (float*)p;
    cudaGetSymbolAddress(&p, g_V);      float* Vb   = (float*)p;
    cudaGetSymbolAddress(&p, g_attn);   float* Ab   = (float*)p;
    cudaGetSymbolAddress(&p, g_scores); float* Sb   = (float*)p;
    cudaGetSymbolAddress(&p, g_t1);     float* t1   = (float*)p;
    cudaGetSymbolAddress(&p, g_query);  float* qry  = (float*)p;
    cudaGetSymbolAddress(&p, g_sim);    float* simb = (float*)p;
    cudaGetSymbolAddress(&p, g_topidx); int*   topi = (int*)p;
    cudaGetSymbolAddress(&p, g_aK);     float* aK   = (float*)p;
    cudaGetSymbolAddress(&p, g_aV);     float* aV   = (float*)p;
    cudaGetSymbolAddress(&p, g_sc2);    float* sc2  = (float*)p;
    cudaGetSymbolAddress(&p, g_mome);   float* mome = (float*)p;
    cudaGetSymbolAddress(&p, g_t2);     float* t2   = (float*)p;

    const int MS = BATCH * SEQ;                        // 8192
    const float scale_base = 1.0f / sqrtf((float)HD);
    const float scale_adpt = 1.0f / sqrtf((float)IDXD);
    dim3 blk(256);
    const int SB = SMEM_BYTES;   // 49152 (== default 48KB dynamic smem cap)

    // 1) Q/K/V projections: [8192,2048] = hs @ W^T
    gemm_mma<true><<<dim3(HID / 128, MS / 128, 1), blk, SB>>>(MS, HID, HID, 1.f, 0.f,
        hs, HID, 0, 0, Wq, HID, 0, 0, Qb, HID, 0, 0, 1, 0, 0);
    gemm_mma<true><<<dim3(HID / 128, MS / 128, 1), blk, SB>>>(MS, HID, HID, 1.f, 0.f,
        hs, HID, 0, 0, Wk, HID, 0, 0, Kb, HID, 0, 0, 1, 0, 0);
    gemm_mma<true><<<dim3(HID / 128, MS / 128, 1), blk, SB>>>(MS, HID, HID, 1.f, 0.f,
        hs, HID, 0, 0, Wv, HID, 0, 0, Vb, HID, 0, 0, 1, 0, 0);

    // 2) base scores (batched over b,h), causal tile-skip
    gemm_mma<true><<<dim3(SEQ / 128, SEQ / 128, BATCH * NHEAD), blk, SB>>>(
        SEQ, SEQ, HD, scale_base, 0.f,
        Qb, HID, (long)SEQ * HID, HD,
        Kb, HID, (long)SEQ * HID, HD,
        Sb, SEQ, (long)NHEAD * SEQ * SEQ, (long)SEQ * SEQ,
        NHEAD, 1, 0);

    // 3) causal softmax
    causal_softmax_k<<<BATCH * NHEAD * SEQ, 256>>>(Sb, SEQ, SEQ);

    // 4) AV: attn_out = P @ V (NN, causal K-limit)
    gemm_mma<false><<<dim3(1, SEQ / 128, BATCH * NHEAD), blk, SB>>>(
        SEQ, HD, SEQ, 1.f, 0.f,
        Sb, SEQ, (long)NHEAD * SEQ * SEQ, (long)SEQ * SEQ,
        Vb, HID, (long)SEQ * HID, HD,
        Ab, HID, (long)SEQ * HID, HD,
        NHEAD, 0, 1);

    // 5) out = attn_out @ Wo^T
    gemm_mma<true><<<dim3(HID / 128, MS / 128, 1), blk, SB>>>(MS, HID, HID, 1.f, 0.f,
        Ab, HID, 0, 0, Wo, HID, 0, 0, out, HID, 0, 0, 1, 0, 0);

    // 6) t1 = hs @ q_in^T   [8192,64]  (fp64: feeds top-k chain)
    gemm_f64acc<<<dim3(RNK / 64, MS / 64, 1), blk>>>(MS, RNK, HID,
        hs, HID, 0, q_in, HID, t1, RNK, 0);

    // 7) query = t1 @ q_out^T   [8192,512]  (fp64)
    gemm_f64acc<<<dim3(IDXD / 64, MS / 64, 1), blk>>>(MS, IDXD, RNK,
        t1, RNK, 0, q_out, RNK, qry, IDXD, 0);

    // 8) sim = query[:512 tokens/batch] @ index_keys^T  (3xTF32, batched)
    gemm_mma<true><<<dim3(NIDX / 128, NTOK / 128, BATCH), blk, SB>>>(
        NTOK, NIDX, IDXD, 1.f, 0.f,
        qry, IDXD, (long)SEQ * IDXD, 0,
        ikeys, IDXD, 0, 0,
        simb, NIDX, (long)NTOK * NIDX, 0,
        1, 0, 0);

    // 9) top-4 per row with fp64 candidate rescoring
    topk4_refine_k<<<BATCH * NTOK, 256>>>(simb, qry, ikeys, topi);

    // 10) gather adapter K/V
    gather_k<<<BATCH * SEQ, 128>>>(topi, ikeys, ivals, aK, aV);

    // 11) adapter scores = query @ aK^T (batched over b, causal tile-skip)
    gemm_mma<true><<<dim3(SEQ / 128, SEQ / 128, BATCH), blk, SB>>>(
        SEQ, SEQ, IDXD, scale_adpt, 0.f,
        qry, IDXD, (long)SEQ * IDXD, 0,
        aK, IDXD, (long)SEQ * IDXD, 0,
        sc2, SEQ, (long)SEQ * SEQ, 0,
        1, 1, 0);

    // 12) causal softmax
    causal_softmax_k<<<BATCH * SEQ, 256>>>(sc2, SEQ, SEQ);

    // 13) mome_attn = P @ aV (NN, causal K-limit)
    gemm_mma<false><<<dim3(IDXD / 128, SEQ / 128, BATCH), blk, SB>>>(
        SEQ, IDXD, SEQ, 1.f, 0.f,
        sc2, SEQ, (long)SEQ * SEQ, 0,
        aV, IDXD, (long)SEQ * IDXD, 0,
        mome, IDXD, (long)SEQ * IDXD, 0,
        1, 0, 1);

    // 14) t2 = mome @ v_in^T   [8192,64]
    gemm_mma<true><<<dim3(1, MS / 128, 1), blk, SB>>>(MS, RNK, IDXD, 1.f, 0.f,
        mome, IDXD, 0, 0, v_in, IDXD, 0, 0, t2, RNK, 0, 0, 1, 0, 0);

    // 15) out += R * (t2 @ v_out^T)
    gemm_mma<true><<<dim3(HID / 128, MS / 128, 1), blk, SB>>>(MS, HID, RNK,
        (float)RNK, 1.f,
        t2, RNK, 0, 0, v_out, RNK, 0, 0, out, HID, 0, 0, 1, 0, 0);
}

// round 12
// speedup vs baseline: 1.4508x; 1.3009x over previous
#include <cuda_runtime.h>
#include <cuda_bf16.h>
#include <math.h>

// ---------------------------------------------------------------------------
// Problem constants
// ---------------------------------------------------------------------------
#define BATCH 4
#define SEQ   2048
#define HID   2048
#define NHEAD 16
#define HD    128
#define RNK   64
#define IDXD  512
#define NIDX  65536
#define TOPK  4
#define NTOK  512          // only first 512 tokens/batch ever attended in adapter

// ---------------------------------------------------------------------------
// Scratch (device globals; no allocation allowed)
// ---------------------------------------------------------------------------
__device__ float g_Q[(size_t)BATCH * SEQ * HID];
__device__ float g_K[(size_t)BATCH * SEQ * HID];
__device__ float g_V[(size_t)BATCH * SEQ * HID];
__device__ float g_attn[(size_t)BATCH * SEQ * HID];
__device__ float g_scores[(size_t)BATCH * NHEAD * SEQ * SEQ];   // 1.07 GB
__device__ float g_t1[(size_t)BATCH * SEQ * RNK];
__device__ float g_query[(size_t)BATCH * SEQ * IDXD];
__device__ float g_sim[(size_t)BATCH * NTOK * NIDX];            // 537 MB (fp32)
__device__ int   g_topidx[BATCH * NTOK * TOPK];
__device__ float g_aK[(size_t)BATCH * SEQ * IDXD];
__device__ float g_aV[(size_t)BATCH * SEQ * IDXD];
__device__ float g_sc2[(size_t)BATCH * SEQ * SEQ];
__device__ float g_mome[(size_t)BATCH * SEQ * IDXD];
__device__ float g_t2[(size_t)BATCH * SEQ * RNK];

// ---------------------------------------------------------------------------
// bf16x4 helpers: a = a0 + a1 (bf16 each, ~16-bit combined mantissa);
// product kept in all 4 cross terms -> per-product error ~2^-16, fp32 accum.
// ---------------------------------------------------------------------------
__device__ __forceinline__ unsigned pack_bf2(float x, float y)
{
    union { __nv_bfloat162 h; unsigned u; } cv;
    cv.h = __floats2bfloat162_rn(x, y);
    return cv.u;
}

// hi/lo split of one float
__device__ __forceinline__ void bsplit(float v, float& hi, float& lo)
{
    __nv_bfloat16 h = __float2bfloat16_rn(v);
    hi = __bfloat162float(h);
    lo = v - hi;
}

__device__ __forceinline__ void mma_bf16(float* c, const unsigned* a, const unsigned* b)
{
    asm volatile(
        "mma.sync.aligned.m16n8k16.row.col.f32.bf16.bf16.f32 "
        "{%0,%1,%2,%3}, {%4,%5,%6,%7}, {%8,%9}, {%0,%1,%2,%3};"
        : "+f"(c[0]), "+f"(c[1]), "+f"(c[2]), "+f"(c[3])
        : "r"(a[0]), "r"(a[1]), "r"(a[2]), "r"(a[3]),
          "r"(b[0]), "r"(b[1]));
}

// ---------------------------------------------------------------------------
// Tensor-core GEMM (bf16x4, ~fp32 accuracy): C = alpha * A * op(B) + beta * C
//   A: [M, K] row-major. TB=true: B [N,K] -> C = A B^T; TB=false: B [K,N].
// Requirements (all call sites satisfy): M % 128 == 0, K % 16 == 0,
//   N % 8 == 0; for TB=false additionally N % 128 == 0.
// Smem: per split s (0=hi, 1=lo): tile[128 rows][4 uint2], where
//   uint2 slot p = ( bf16x2(k=2p,2p+1), bf16x2(k=2p+8,2p+9) ).
// Fragment loads are contiguous LDS.64 (conflict-free, no swizzle).
// Phase-sequential splits keep live fragment regs at 32 -> no spills @2 CTA/SM.
// ---------------------------------------------------------------------------
template<bool TB>
__global__ __launch_bounds__(256, 2)
void gemm_mma(int M, int N, int Kd, float alpha, float beta,
              const float* __restrict__ A, int lda, long sAb, long sAh,
              const float* __restrict__ B, int ldb, long sBb, long sBh,
              float* __restrict__ C, int ldc, long sCb, long sCh,
              int nh, int causal_skip, int k_limit)
{
    int z  = blockIdx.z;
    int bb = z / nh, hh = z - bb * nh;
    A += (long)bb * sAb + (long)hh * sAh;
    B += (long)bb * sBb + (long)hh * sBh;
    C += (long)bb * sCb + (long)hh * sCh;

    int row0 = blockIdx.y << 7;
    int col0 = blockIdx.x << 7;
    if (causal_skip && col0 > row0 + 127) return;

    int kEff = Kd;
    if (k_limit) { int lim = row0 + 128; if (lim < kEff) kEff = lim; }

    __shared__ uint2 A0s[512], A1s[512];   // [row*4 + slot]
    __shared__ uint2 B0s[512], B1s[512];   // [n*4 + slot]

    int tid  = threadIdx.x;
    int warp = tid >> 5, lane = tid & 31;
    int wm = warp & 1;          // m offset 0/64
    int wn = warp >> 1;         // n offset 0/32/64/96
    int grp = lane >> 2;        // 0..7
    int tig = lane & 3;         // 0..3

    // hoisted fragment addresses (uint2 indices)
    int aoff[4][2], boff[4];
#pragma unroll
    for (int i = 0; i < 4; i++) {
        int r = (wm << 6) + (i << 4) + grp;
        aoff[i][0] = r * 4 + tig;
        aoff[i][1] = (r + 8) * 4 + tig;
    }
#pragma unroll
    for (int j = 0; j < 4; j++) {
        int n = (wn << 5) + (j << 3) + grp;
        boff[j] = n * 4 + tig;
    }

    float acc[16][4];
#pragma unroll
    for (int f = 0; f < 16; f++)
#pragma unroll
        for (int r = 0; r < 4; r++) acc[f][r] = 0.f;

    unsigned* A0w = (unsigned*)A0s; unsigned* A1w = (unsigned*)A1s;
    unsigned* B0w = (unsigned*)B0s; unsigned* B1w = (unsigned*)B1s;

    for (int k0 = 0; k0 < kEff; k0 += 16) {
        // ---- fill A tile: 128 rows x 16 k (2 float4 per thread) ----
#pragma unroll
        for (int s = 0; s < 2; s++) {
            int id = (tid << 1) + s;            // 0..511
            int m = id >> 2, kk = (id & 3) << 2;   // kk in {0,4,8,12}
            float4 v = *(const float4*)(A + (long)(row0 + m) * lda + (k0 + kk));
            float h0, l0, h1, l1, h2, l2, h3, l3;
            bsplit(v.x, h0, l0); bsplit(v.y, h1, l1);
            bsplit(v.z, h2, l2); bsplit(v.w, h3, l3);
            int p0 = (kk & 7) >> 1;             // 0 or 2
            int hf = (kk >> 3) & 1;             // hi-k half flag
            int base = (m << 2) + p0;
            A0w[(base << 1) + hf]       = pack_bf2(h0, h1);
            A0w[((base + 1) << 1) + hf] = pack_bf2(h2, h3);
            A1w[(base << 1) + hf]       = pack_bf2(l0, l1);
            A1w[((base + 1) << 1) + hf] = pack_bf2(l2, l3);
        }
        // ---- fill B tile as [n][k] ----
        if (TB) {
#pragma unroll
            for (int s = 0; s < 2; s++) {
                int id = (tid << 1) + s;
                int n = id >> 2, kk = (id & 3) << 2;
                int gn = col0 + n;
                float4 v = make_float4(0.f, 0.f, 0.f, 0.f);
                if (gn < N) v = *(const float4*)(B + (long)gn * ldb + (k0 + kk));
                float h0, l0, h1, l1, h2, l2, h3, l3;
                bsplit(v.x, h0, l0); bsplit(v.y, h1, l1);
                bsplit(v.z, h2, l2); bsplit(v.w, h3, l3);
                int p0 = (kk & 7) >> 1;
                int hf = (kk >> 3) & 1;
                int base = (n << 2) + p0;
                B0w[(base << 1) + hf]       = pack_bf2(h0, h1);
                B0w[((base + 1) << 1) + hf] = pack_bf2(h2, h3);
                B1w[(base << 1) + hf]       = pack_bf2(l0, l1);
                B1w[((base + 1) << 1) + hf] = pack_bf2(l2, l3);
            }
        } else {
            // B is [K, N]; N % 128 == 0 at all TB=false call sites.
            // Scalar elements -> 2-byte smem stores.
            unsigned short* B0h = (unsigned short*)B0s;
            unsigned short* B1h = (unsigned short*)B1s;
#pragma unroll
            for (int s = 0; s < 8; s++) {
                int id = (s << 8) + tid;        // 0..2047
                int kk = id >> 7, n = id & 127;
                float v = B[(long)(k0 + kk) * ldb + (col0 + n)];
                float hi, lo;
                bsplit(v, hi, lo);
                int p  = (kk & 7) >> 1;
                int hf = (kk >> 3) & 1;
                int e  = kk & 1;
                int idx = ((((n << 2) + p) << 1) + hf) * 2 + e;
                union { __nv_bfloat16 b; unsigned short u; } c0, c1;
                c0.b = __float2bfloat16_rn(hi);
                c1.b = __float2bfloat16_rn(lo);
                B0h[idx] = c0.u;
                B1h[idx] = c1.u;
            }
        }
        __syncthreads();

        // B fragments (both splits, all j): 8 x LDS.64, 16 regs, live all phases
        unsigned b0f[4][2], b1f[4][2];
#pragma unroll
        for (int j = 0; j < 4; j++) {
            uint2 v0 = B0s[boff[j]];
            uint2 v1 = B1s[boff[j]];
            b0f[j][0] = v0.x; b0f[j][1] = v0.y;
            b1f[j][0] = v1.x; b1f[j][1] = v1.y;
        }
        // phase 0: a0 fragments -> a0*b0, a0*b1
        {
            unsigned af[4][4];
#pragma unroll
            for (int i = 0; i < 4; i++) {
                uint2 u0 = A0s[aoff[i][0]];
                uint2 u1 = A0s[aoff[i][1]];
                af[i][0] = u0.x; af[i][1] = u1.x; af[i][2] = u0.y; af[i][3] = u1.y;
            }
#pragma unroll
            for (int j = 0; j < 4; j++)
#pragma unroll
                for (int i = 0; i < 4; i++) mma_bf16(acc[i * 4 + j], af[i], b0f[j]);
#pragma unroll
            for (int j = 0; j < 4; j++)
#pragma unroll
                for (int i = 0; i < 4; i++) mma_bf16(acc[i * 4 + j], af[i], b1f[j]);
        }
        // phase 1: a1 fragments -> a1*b0, a1*b1
        {
            unsigned af[4][4];
#pragma unroll
            for (int i = 0; i < 4; i++) {
                uint2 u0 = A1s[aoff[i][0]];
                uint2 u1 = A1s[aoff[i][1]];
                af[i][0] = u0.x; af[i][1] = u1.x; af[i][2] = u0.y; af[i][3] = u1.y;
            }
#pragma unroll
            for (int j = 0; j < 4; j++)
#pragma unroll
                for (int i = 0; i < 4; i++) mma_bf16(acc[i * 4 + j], af[i], b0f[j]);
#pragma unroll
            for (int j = 0; j < 4; j++)
#pragma unroll
                for (int i = 0; i < 4; i++) mma_bf16(acc[i * 4 + j], af[i], b1f[j]);
        }
        __syncthreads();
    }

    // ---- epilogue ----
#pragma unroll
    for (int i = 0; i < 4; i++) {
#pragma unroll
        for (int j = 0; j < 4; j++) {
            float* c = acc[i * 4 + j];
            int gm = row0 + (wm << 6) + (i << 4) + grp;
            int gn = col0 + (wn << 5) + (j << 3) + (tig << 1);
            if (gn < N) {     // N % 8 == 0 -> gn+1 < N too
                long o0 = (long)gm * ldc + gn;
                long o1 = (long)(gm + 8) * ldc + gn;
                float2 r0, r1;
                r0.x = alpha * c[0]; r0.y = alpha * c[1];
                r1.x = alpha * c[2]; r1.y = alpha * c[3];
                if (beta != 0.f) {
                    float2 p0 = *(float2*)(C + o0);
                    float2 p1 = *(float2*)(C + o1);
                    r0.x += beta * p0.x; r0.y += beta * p0.y;
                    r1.x += beta * p1.x; r1.y += beta * p1.y;
                }
                *(float2*)(C + o0) = r0;
                *(float2*)(C + o1) = r1;
            }
        }
    }
}

// ---------------------------------------------------------------------------
// fp64-accumulated GEMM (C = A * B^T) — small t1/query chain only, so top-k
// rescoring inputs are exactly rounded.
// ---------------------------------------------------------------------------
__global__ __launch_bounds__(256)
void gemm_f64acc(int M, int N, int Kd,
                 const float* __restrict__ A, int lda, long sAb,
                 const float* __restrict__ B, int ldb,
                 float* __restrict__ C, int ldc, long sCb)
{
    int b = blockIdx.z;
    A += (long)b * sAb;
    C += (long)b * sCb;

    int row0 = blockIdx.y << 6;
    int col0 = blockIdx.x << 6;

    __shared__ float As[8][68];
    __shared__ float Bs[8][68];

    int tid = threadIdx.x;
    int tx = tid & 15, ty = tid >> 4;

    double acc[4][4];
#pragma unroll
    for (int i = 0; i < 4; i++)
#pragma unroll
        for (int j = 0; j < 4; j++) acc[i][j] = 0.0;

    for (int k0 = 0; k0 < Kd; k0 += 8) {
#pragma unroll
        for (int l = 0; l < 2; l++) {
            int idx = tid + (l << 8);
            int m = idx >> 3, k = idx & 7;
            int gm = row0 + m, gk = k0 + k;
            As[k][m] = (gm < M && gk < Kd) ? A[(long)gm * lda + gk] : 0.f;
            int gn = col0 + m;
            Bs[k][m] = (gn < N && gk < Kd) ? B[(long)gn * ldb + gk] : 0.f;
        }
        __syncthreads();

#pragma unroll
        for (int kk = 0; kk < 8; kk++) {
            float a[4], bb[4];
#pragma unroll
            for (int i = 0; i < 4; i++) a[i]  = As[kk][(ty << 2) + i];
#pragma unroll
            for (int j = 0; j < 4; j++) bb[j] = Bs[kk][(tx << 2) + j];
#pragma unroll
            for (int i = 0; i < 4; i++)
#pragma unroll
                for (int j = 0; j < 4; j++)
                    acc[i][j] = fma((double)a[i], (double)bb[j], acc[i][j]);
        }
        __syncthreads();
    }

#pragma unroll
    for (int i = 0; i < 4; i++) {
        int gm = row0 + (ty << 2) + i;
        if (gm >= M) continue;
#pragma unroll
        for (int j = 0; j < 4; j++) {
            int gn = col0 + (tx << 2) + j;
            if (gn >= N) continue;
            C[(long)gm * ldc + gn] = (float)acc[i][j];
        }
    }
}

// ---------------------------------------------------------------------------
// Causal row softmax on S[row, :T]; valid cols j <= q (q = row % L).
// ---------------------------------------------------------------------------
__global__ void causal_softmax_k(float* __restrict__ S, int L, int T)
{
    long row = blockIdx.x;
    int q = (int)(row % L);
    float* p = S + row * (long)T;
    int n = q + 1;
    int tid = threadIdx.x;
    __shared__ float red[32];

    float m = -INFINITY;
    for (int j = tid; j < n; j += blockDim.x) m = fmaxf(m, p[j]);
#pragma unroll
    for (int o = 16; o; o >>= 1) m = fmaxf(m, __shfl_xor_sync(0xffffffffu, m, o));
    if ((tid & 31) == 0) red[tid >> 5] = m;
    __syncthreads();
    if (tid < 32) {
        float v = (tid < (int)(blockDim.x >> 5)) ? red[tid] : -INFINITY;
#pragma unroll
        for (int o = 16; o; o >>= 1) v = fmaxf(v, __shfl_xor_sync(0xffffffffu, v, o));
        if (tid == 0) red[0] = v;
    }
    __syncthreads();
    m = red[0];
    __syncthreads();

    float s = 0.f;
    for (int j = tid; j < n; j += blockDim.x) {
        float e = expf(p[j] - m);
        p[j] = e;
        s += e;
    }
#pragma unroll
    for (int o = 16; o; o >>= 1) s += __shfl_xor_sync(0xffffffffu, s, o);
    if ((tid & 31) == 0) red[tid >> 5] = s;
    __syncthreads();
    if (tid < 32) {
        float v = (tid < (int)(blockDim.x >> 5)) ? red[tid] : 0.f;
#pragma unroll
        for (int o = 16; o; o >>= 1) v += __shfl_xor_sync(0xffffffffu, v, o);
        if (tid == 0) red[0] = v;
    }
    __syncthreads();
    float inv = 1.f / red[0];
    for (int j = tid; j < n; j += blockDim.x) p[j] *= inv;
    for (int j = n + tid; j < T; j += blockDim.x) p[j] = 0.f;
}

// ---------------------------------------------------------------------------
// Top-4 with fp64 refinement (phases: stripe top-4 -> serial top-16 ->
// fp64 rescore -> top-4). Tie-break: lower index (matches jax.lax.top_k).
// ---------------------------------------------------------------------------
__global__ __launch_bounds__(256)
void topk4_refine_k(const float* __restrict__ sim,
                    const float* __restrict__ qry,
                    const float* __restrict__ keys,
                    int* __restrict__ out)
{
    long row = blockIdx.x;
    int b   = (int)(row >> 9);
    int tok = (int)(row & (NTOK - 1));
    const float* p = sim + row * (long)NIDX;
    int tid = threadIdx.x;

    float v0 = -INFINITY, v1 = -INFINITY, v2 = -INFINITY, v3 = -INFINITY;
    int   i0 = 0x7fffffff, i1 = 0x7fffffff, i2 = 0x7fffffff, i3 = 0x7fffffff;

    for (int j = tid; j < NIDX; j += 256) {
        float x = p[j];
        if (x > v3 || (x == v3 && j < i3)) {
            if (x > v0 || (x == v0 && j < i0)) {
                v3 = v2; i3 = i2; v2 = v1; i2 = i1; v1 = v0; i1 = i0; v0 = x; i0 = j;
            } else if (x > v1 || (x == v1 && j < i1)) {
                v3 = v2; i3 = i2; v2 = v1; i2 = i1; v1 = x; i1 = j;
            } else if (x > v2 || (x == v2 && j < i2)) {
                v3 = v2; i3 = i2; v2 = x; i2 = j;
            } else {
                v3 = x; i3 = j;
            }
        }
    }

    __shared__ float sv[1024];
    __shared__ int   si[1024];
    sv[tid * 4 + 0] = v0; si[tid * 4 + 0] = i0;
    sv[tid * 4 + 1] = v1; si[tid * 4 + 1] = i1;
    sv[tid * 4 + 2] = v2; si[tid * 4 + 2] = i2;
    sv[tid * 4 + 3] = v3; si[tid * 4 + 3] = i3;
    __syncthreads();

    __shared__ int   cidx[16];
    __shared__ float cval[16];
    if (tid == 0) {
        for (int r = 0; r < 16; r++) {
            float best = -INFINITY; int bid = 0x7fffffff; int bp = -1;
            for (int i = 0; i < 1024; i++) {
                float x = sv[i];
                if (x > best || (x == best && si[i] < bid)) { best = x; bid = si[i]; bp = i; }
            }
            cidx[r] = bid;
            sv[bp] = -INFINITY; si[bp] = 0x7fffffff;
        }
    }
    __syncthreads();

    {
        int warp = tid >> 5, lane = tid & 31;
        int c = (warp << 1) + (lane >> 4);
        int l = lane & 15;
        const float* qrow = qry + ((long)b * SEQ + tok) * IDXD;
        const float* krow = keys + (long)cidx[c] * IDXD;
        double s = 0.0;
        for (int t = l; t < IDXD; t += 16)
            s = fma((double)qrow[t], (double)krow[t], s);
#pragma unroll
        for (int o = 8; o; o >>= 1) s += __shfl_xor_sync(0xffffffffu, s, o, 16);
        if (l == 0) cval[c] = (float)s;
    }
    __syncthreads();

    if (tid == 0) {
        float lv[16]; int li[16];
#pragma unroll
        for (int i = 0; i < 16; i++) { lv[i] = cval[i]; li[i] = cidx[i]; }
        for (int r = 0; r < TOPK; r++) {
            float best = -INFINITY; int bid = 0x7fffffff; int bp = -1;
#pragma unroll
            for (int i = 0; i < 16; i++) {
                float x = lv[i];
                if (x > best || (x == best && li[i] < bid)) { best = x; bid = li[i]; bp = i; }
            }
            out[row * TOPK + r] = bid;
            lv[bp] = -INFINITY; li[bp] = 0x7fffffff;
        }
    }
}

// ---------------------------------------------------------------------------
// Gather adapter K/V rows
// ---------------------------------------------------------------------------
__global__ void gather_k(const int* __restrict__ tidx,
                         const float* __restrict__ keys,
                         const float* __restrict__ vals,
                         float* __restrict__ aK, float* __restrict__ aV)
{
    int blk = blockIdx.x;
    int b = blk >> 11;
    int j = blk & 2047;
    int id = tidx[((b * NTOK + (j >> 2)) << 2) + (j & 3)];
    const float4* ks = (const float4*)(keys + (long)id * IDXD);
    const float4* vs = (const float4*)(vals + (long)id * IDXD);
    float4* dk = (float4*)(aK + (long)blk * IDXD);
    float4* dv = (float4*)(aV + (long)blk * IDXD);
    int t = threadIdx.x;
    dk[t] = ks[t];
    dv[t] = vs[t];
}

// ---------------------------------------------------------------------------
// Host launch
// ---------------------------------------------------------------------------
extern "C" void kernel_launch(void* const* d_in, const int* in_sizes, int n_in,
                              void* d_out, int out_size)
{
    const float* hs    = (const float*)d_in[0];
    const float* Wq    = (const float*)d_in[1];
    const float* Wk    = (const float*)d_in[2];
    const float* Wv    = (const float*)d_in[3];
    const float* Wo    = (const float*)d_in[4];
    const float* q_in  = (const float*)d_in[5];
    const float* q_out = (const float*)d_in[6];
    const float* v_in  = (const float*)d_in[7];
    const float* v_out = (const float*)d_in[8];
    const float* ikeys = (const float*)d_in[9];
    const float* ivals = (const float*)d_in[10];
    float* out = (float*)d_out;

    void* p;
    cudaGetSymbolAddress(&p, g_Q);      float* Qb   = (float*)p;
    cudaGetSymbolAddress(&p, g_K);      float* Kb   = (float*)p;
    cudaGetSymbolAddress(&p, g_V);      float* Vb   = (float*)p;
    cudaGetSymbolAddress(&p, g_attn);   float* Ab   = (float*)p;
    cudaGetSymbolAddress(&p, g_scores); float* Sb   = (float*)p;
    cudaGetSymbolAddress(&p, g_t1);     float* t1   = (float*)p;
    cudaGetSymbolAddress(&p, g_query);  float* qry  = (float*)p;
    cudaGetSymbolAddress(&p, g_sim);    float* simb = (float*)p;
    cudaGetSymbolAddress(&p, g_topidx); int*   topi = (int*)p;
    cudaGetSymbolAddress(&p, g_aK);     float* aK   = (float*)p;
    cudaGetSymbolAddress(&p, g_aV);     float* aV   = (float*)p;
    cudaGetSymbolAddress(&p, g_sc2);    float* sc2  = (float*)p;
    cudaGetSymbolAddress(&p, g_mome);   float* mome = (float*)p;
    cudaGetSymbolAddress(&p, g_t2);     float* t2   = (float*)p;

    const int MS = BATCH * SEQ;                        // 8192
    const float scale_base = 1.0f / sqrtf((float)HD);
    const float scale_adpt = 1.0f / sqrtf((float)IDXD);
    dim3 blk(256);

    // 1) Q/K/V projections: [8192,2048] = hs @ W^T
    gemm_mma<true><<<dim3(HID / 128, MS / 128, 1), blk>>>(MS, HID, HID, 1.f, 0.f,
        hs, HID, 0, 0, Wq, HID, 0, 0, Qb, HID, 0, 0, 1, 0, 0);
    gemm_mma<true><<<dim3(HID / 128, MS / 128, 1), blk>>>(MS, HID, HID, 1.f, 0.f,
        hs, HID, 0, 0, Wk, HID, 0, 0, Kb, HID, 0, 0, 1, 0, 0);
    gemm_mma<true><<<dim3(HID / 128, MS / 128, 1), blk>>>(MS, HID, HID, 1.f, 0.f,
        hs, HID, 0, 0, Wv, HID, 0, 0, Vb, HID, 0, 0, 1, 0, 0);

    // 2) base scores (batched over b,h), causal tile-skip
    gemm_mma<true><<<dim3(SEQ / 128, SEQ / 128, BATCH * NHEAD), blk>>>(
        SEQ, SEQ, HD, scale_base, 0.f,
        Qb, HID, (long)SEQ * HID, HD,
        Kb, HID, (long)SEQ * HID, HD,
        Sb, SEQ, (long)NHEAD * SEQ * SEQ, (long)SEQ * SEQ,
        NHEAD, 1, 0);

    // 3) causal softmax
    causal_softmax_k<<<BATCH * NHEAD * SEQ, 256>>>(Sb, SEQ, SEQ);

    // 4) AV: attn_out = P @ V (NN, causal K-limit)
    gemm_mma<false><<<dim3(1, SEQ / 128, BATCH * NHEAD), blk>>>(
        SEQ, HD, SEQ, 1.f, 0.f,
        Sb, SEQ, (long)NHEAD * SEQ * SEQ, (long)SEQ * SEQ,
        Vb, HID, (long)SEQ * HID, HD,
        Ab, HID, (long)SEQ * HID, HD,
        NHEAD, 0, 1);

    // 5) out = attn_out @ Wo^T
    gemm_mma<true><<<dim3(HID / 128, MS / 128, 1), blk>>>(MS, HID, HID, 1.f, 0.f,
        Ab, HID, 0, 0, Wo, HID, 0, 0, out, HID, 0, 0, 1, 0, 0);

    // 6) t1 = hs @ q_in^T   [8192,64]  (fp64: feeds top-k chain)
    gemm_f64acc<<<dim3(RNK / 64, MS / 64, 1), blk>>>(MS, RNK, HID,
        hs, HID, 0, q_in, HID, t1, RNK, 0);

    // 7) query = t1 @ q_out^T   [8192,512]  (fp64)
    gemm_f64acc<<<dim3(IDXD / 64, MS / 64, 1), blk>>>(MS, IDXD, RNK,
        t1, RNK, 0, q_out, RNK, qry, IDXD, 0);

    // 8) sim = query[:512 tokens/batch] @ index_keys^T  (bf16x4, batched)
    gemm_mma<true><<<dim3(NIDX / 128, NTOK / 128, BATCH), blk>>>(
        NTOK, NIDX, IDXD, 1.f, 0.f,
        qry, IDXD, (long)SEQ * IDXD, 0,
        ikeys, IDXD, 0, 0,
        simb, NIDX, (long)NTOK * NIDX, 0,
        1, 0, 0);

    // 9) top-4 per row with fp64 candidate rescoring
    topk4_refine_k<<<BATCH * NTOK, 256>>>(simb, qry, ikeys, topi);

    // 10) gather adapter K/V
    gather_k<<<BATCH * SEQ, 128>>>(topi, ikeys, ivals, aK, aV);

    // 11) adapter scores = query @ aK^T (batched over b, causal tile-skip)
    gemm_mma<true><<<dim3(SEQ / 128, SEQ / 128, BATCH), blk>>>(
        SEQ, SEQ, IDXD, scale_adpt, 0.f,
        qry, IDXD, (long)SEQ * IDXD, 0,
        aK, IDXD, (long)SEQ * IDXD, 0,
        sc2, SEQ, (long)SEQ * SEQ, 0,
        1, 1, 0);

    // 12) causal softmax
    causal_softmax_k<<<BATCH * SEQ, 256>>>(sc2, SEQ, SEQ);

    // 13) mome_attn = P @ aV (NN, causal K-limit)
    gemm_mma<false><<<dim3(IDXD / 128, SEQ / 128, BATCH), blk>>>(
        SEQ, IDXD, SEQ, 1.f, 0.f,
        sc2, SEQ, (long)SEQ * SEQ, 0,
        aV, IDXD, (long)SEQ * IDXD, 0,
        mome, IDXD, (long)SEQ * IDXD, 0,
        1, 0, 1);

    // 14) t2 = mome @ v_in^T   [8192,64]
    gemm_mma<true><<<dim3(1, MS / 128, 1), blk>>>(MS, RNK, IDXD, 1.f, 0.f,
        mome, IDXD, 0, 0, v_in, IDXD, 0, 0, t2, RNK, 0, 0, 1, 0, 0);

    // 15) out += R * (t2 @ v_out^T)
    gemm_mma<true><<<dim3(HID / 128, MS / 128, 1), blk>>>(MS, HID, RNK,
        (float)RNK, 1.f,
        t2, RNK, 0, 0, v_out, RNK, 0, 0, out, HID, 0, 0, 1, 0, 0);
}

// round 15
// speedup vs baseline: 2.2116x; 1.5245x over previous
#include <cuda_runtime.h>
#include <cuda_bf16.h>
#include <math.h>

// ---------------------------------------------------------------------------
// Problem constants
// ---------------------------------------------------------------------------
#define BATCH 4
#define SEQ   2048
#define HID   2048
#define NHEAD 16
#define HD    128
#define RNK   64
#define IDXD  512
#define NIDX  65536
#define TOPK  4
#define NTOK  512          // only first 512 tokens/batch ever attended in adapter

// ---------------------------------------------------------------------------
// Scratch (device globals; no allocation allowed)
// ---------------------------------------------------------------------------
__device__ float g_Q[(size_t)BATCH * SEQ * HID];
__device__ float g_K[(size_t)BATCH * SEQ * HID];
__device__ float g_V[(size_t)BATCH * SEQ * HID];
__device__ float g_attn[(size_t)BATCH * SEQ * HID];
__device__ float g_scores[(size_t)BATCH * NHEAD * SEQ * SEQ];   // 1.07 GB
__device__ float g_t1[(size_t)BATCH * SEQ * RNK];
__device__ float g_query[(size_t)BATCH * SEQ * IDXD];
__device__ float g_sim[(size_t)BATCH * NTOK * NIDX];            // 537 MB (fp32)
__device__ int   g_topidx[BATCH * NTOK * TOPK];
__device__ float g_aK[(size_t)BATCH * SEQ * IDXD];
__device__ float g_aV[(size_t)BATCH * SEQ * IDXD];
__device__ float g_sc2[(size_t)BATCH * SEQ * SEQ];
__device__ float g_mome[(size_t)BATCH * SEQ * IDXD];
__device__ float g_t2[(size_t)BATCH * SEQ * RNK];

// ---------------------------------------------------------------------------
// bf16x4 helpers (3 cross terms kept; a1*b1 ~2^-18 dropped)
// ---------------------------------------------------------------------------
__device__ __forceinline__ unsigned pack_bf2(float x, float y)
{
    union { __nv_bfloat162 h; unsigned u; } cv;
    cv.h = __floats2bfloat162_rn(x, y);
    return cv.u;
}

__device__ __forceinline__ void bsplit(float v, float& hi, float& lo)
{
    __nv_bfloat16 h = __float2bfloat16_rn(v);
    hi = __bfloat162float(h);
    lo = v - hi;
}

__device__ __forceinline__ void mma_bf16(float* c, const unsigned* a, const unsigned* b)
{
    asm volatile(
        "mma.sync.aligned.m16n8k16.row.col.f32.bf16.bf16.f32 "
        "{%0,%1,%2,%3}, {%4,%5,%6,%7}, {%8,%9}, {%0,%1,%2,%3};"
        : "+f"(c[0]), "+f"(c[1]), "+f"(c[2]), "+f"(c[3])
        : "r"(a[0]), "r"(a[1]), "r"(a[2]), "r"(a[3]),
          "r"(b[0]), "r"(b[1]));
}

// split a float4 (k..k+3 of one row) and store hi/lo bf16x2 pairs into tile
__device__ __forceinline__ void st_split4(uint2* S0, uint2* S1, float4 v, int id)
{
    int m = id >> 2, kk = (id & 3) << 2;
    float h0, l0, h1, l1, h2, l2, h3, l3;
    bsplit(v.x, h0, l0); bsplit(v.y, h1, l1);
    bsplit(v.z, h2, l2); bsplit(v.w, h3, l3);
    int p0 = (kk & 7) >> 1;
    int hf = (kk >> 3) & 1;
    unsigned* W0 = (unsigned*)S0;
    unsigned* W1 = (unsigned*)S1;
    int base = (m << 2) + p0;
    W0[(base << 1) + hf]       = pack_bf2(h0, h1);
    W0[((base + 1) << 1) + hf] = pack_bf2(h2, h3);
    W1[(base << 1) + hf]       = pack_bf2(l0, l1);
    W1[((base + 1) << 1) + hf] = pack_bf2(l2, l3);
}

// ---------------------------------------------------------------------------
// Tensor-core GEMM (bf16x3, ~fp32 accuracy), double-buffered smem:
//   C = alpha * A * op(B) + beta * C
//   A: [M, K] row-major. TB=true: B [N,K] -> C = A B^T; TB=false: B [K,N].
// Requirements: M % 128 == 0, K % 16 == 0, N % 8 == 0 (TB=false: N % 128 == 0).
// One barrier per k-tile; tile k+1's LDGs issued during tile k's MMA.
// ---------------------------------------------------------------------------
template<bool TB>
__global__ __launch_bounds__(256, 2)
void gemm_mma(int M, int N, int Kd, float alpha, float beta,
              const float* __restrict__ A, int lda, long sAb, long sAh,
              const float* __restrict__ B, int ldb, long sBb, long sBh,
              float* __restrict__ C, int ldc, long sCb, long sCh,
              int nh, int causal_skip, int k_limit)
{
    int z  = blockIdx.z;
    int bb = z / nh, hh = z - bb * nh;
    A += (long)bb * sAb + (long)hh * sAh;
    B += (long)bb * sBb + (long)hh * sBh;
    C += (long)bb * sCb + (long)hh * sCh;

    int row0 = blockIdx.y << 7;
    int col0 = blockIdx.x << 7;
    if (causal_skip && col0 > row0 + 127) return;

    int kEff = Kd;
    if (k_limit) { int lim = row0 + 128; if (lim < kEff) kEff = lim; }
    int nk = kEff >> 4;                       // k-tiles (K % 16 == 0)

    __shared__ uint2 A0s[2][512], A1s[2][512];   // [buf][row*4+slot]
    __shared__ uint2 B0s[2][512], B1s[2][512];   // 32 KB total

    int tid  = threadIdx.x;
    int warp = tid >> 5, lane = tid & 31;
    int wm = warp & 1;          // m offset 0/64
    int wn = warp >> 1;         // n offset 0/32/64/96
    int grp = lane >> 2;        // 0..7
    int tig = lane & 3;         // 0..3

    // hoisted fragment addresses (uint2 indices)
    int aoff[4][2], boff[4];
#pragma unroll
    for (int i = 0; i < 4; i++) {
        int r = (wm << 6) + (i << 4) + grp;
        aoff[i][0] = r * 4 + tig;
        aoff[i][1] = (r + 8) * 4 + tig;
    }
#pragma unroll
    for (int j = 0; j < 4; j++) {
        int n = (wn << 5) + (j << 3) + grp;
        boff[j] = n * 4 + tig;
    }

    float acc[16][4];
#pragma unroll
    for (int f = 0; f < 16; f++)
#pragma unroll
        for (int r = 0; r < 4; r++) acc[f][r] = 0.f;

    // ---- prefetch registers ----
    float4 pa0, pa1;
    float4 pbv0, pbv1;          // TB=true
    float  pbs[8];              // TB=false

    // A addressing (fixed per thread)
    int a_m0 = (tid << 1) >> 2,        a_k0 = (((tid << 1) & 3) << 2);
    int a_m1 = ((tid << 1) + 1) >> 2,  a_k1 = ((((tid << 1) + 1) & 3) << 2);

    auto ldA = [&](int k0) {
        pa0 = *(const float4*)(A + (long)(row0 + a_m0) * lda + (k0 + a_k0));
        pa1 = *(const float4*)(A + (long)(row0 + a_m1) * lda + (k0 + a_k1));
    };
    auto stA = [&](int buf) {
        st_split4(A0s[buf], A1s[buf], pa0, (tid << 1));
        st_split4(A0s[buf], A1s[buf], pa1, (tid << 1) + 1);
    };
    auto ldB = [&](int k0) {
        if (TB) {
            int gn0 = col0 + a_m0, gn1 = col0 + a_m1;
            pbv0 = (gn0 < N) ? *(const float4*)(B + (long)gn0 * ldb + (k0 + a_k0))
                             : make_float4(0.f, 0.f, 0.f, 0.f);
            pbv1 = (gn1 < N) ? *(const float4*)(B + (long)gn1 * ldb + (k0 + a_k1))
                             : make_float4(0.f, 0.f, 0.f, 0.f);
        } else {
#pragma unroll
            for (int s = 0; s < 8; s++) {
                int id = (s << 8) + tid;
                int kk = id >> 7, n = id & 127;
                pbs[s] = B[(long)(k0 + kk) * ldb + (col0 + n)];
            }
        }
    };
    auto stB = [&](int buf) {
        if (TB) {
            st_split4(B0s[buf], B1s[buf], pbv0, (tid << 1));
            st_split4(B0s[buf], B1s[buf], pbv1, (tid << 1) + 1);
        } else {
            unsigned short* B0h = (unsigned short*)B0s[buf];
            unsigned short* B1h = (unsigned short*)B1s[buf];
#pragma unroll
            for (int s = 0; s < 8; s++) {
                int id = (s << 8) + tid;
                int kk = id >> 7, n = id & 127;
                float hi, lo;
                bsplit(pbs[s], hi, lo);
                int p  = (kk & 7) >> 1;
                int hf = (kk >> 3) & 1;
                int e  = kk & 1;
                int idx = ((((n << 2) + p) << 1) + hf) * 2 + e;
                union { __nv_bfloat16 b; unsigned short u; } c0, c1;
                c0.b = __float2bfloat16_rn(hi);
                c1.b = __float2bfloat16_rn(lo);
                B0h[idx] = c0.u;
                B1h[idx] = c1.u;
            }
        }
    };

    // prologue: fill buffer 0
    ldA(0); ldB(0);
    stA(0); stB(0);
    int cur = 0;

    for (int t = 0; t < nk; t++) {
        __syncthreads();                    // buf[cur] visible to all
        bool pf = (t + 1 < nk);
        if (pf) { ldA((t + 1) << 4); ldB((t + 1) << 4); }

        // B fragments (both splits): 8 x LDS.64
        unsigned b0f[4][2], b1f[4][2];
#pragma unroll
        for (int j = 0; j < 4; j++) {
            uint2 v0 = B0s[cur][boff[j]];
            uint2 v1 = B1s[cur][boff[j]];
            b0f[j][0] = v0.x; b0f[j][1] = v0.y;
            b1f[j][0] = v1.x; b1f[j][1] = v1.y;
        }
        {   // a0 passes: a0*b0, a0*b1
            unsigned af[4][4];
#pragma unroll
            for (int i = 0; i < 4; i++) {
                uint2 u0 = A0s[cur][aoff[i][0]];
                uint2 u1 = A0s[cur][aoff[i][1]];
                af[i][0] = u0.x; af[i][1] = u1.x; af[i][2] = u0.y; af[i][3] = u1.y;
            }
#pragma unroll
            for (int j = 0; j < 4; j++)
#pragma unroll
                for (int i = 0; i < 4; i++) mma_bf16(acc[i * 4 + j], af[i], b0f[j]);
#pragma unroll
            for (int j = 0; j < 4; j++)
#pragma unroll
                for (int i = 0; i < 4; i++) mma_bf16(acc[i * 4 + j], af[i], b1f[j]);
        }
        {   // a1 pass: a1*b0   (a1*b1 ~2^-18 dropped)
            unsigned af[4][4];
#pragma unroll
            for (int i = 0; i < 4; i++) {
                uint2 u0 = A1s[cur][aoff[i][0]];
                uint2 u1 = A1s[cur][aoff[i][1]];
                af[i][0] = u0.x; af[i][1] = u1.x; af[i][2] = u0.y; af[i][3] = u1.y;
            }
#pragma unroll
            for (int j = 0; j < 4; j++)
#pragma unroll
                for (int i = 0; i < 4; i++) mma_bf16(acc[i * 4 + j], af[i], b0f[j]);
        }

        if (pf) { stA(cur ^ 1); stB(cur ^ 1); }
        cur ^= 1;
    }

    // ---- epilogue ----
#pragma unroll
    for (int i = 0; i < 4; i++) {
#pragma unroll
        for (int j = 0; j < 4; j++) {
            float* c = acc[i * 4 + j];
            int gm = row0 + (wm << 6) + (i << 4) + grp;
            int gn = col0 + (wn << 5) + (j << 3) + (tig << 1);
            if (gn < N) {     // N % 8 == 0 -> gn+1 < N too
                long o0 = (long)gm * ldc + gn;
                long o1 = (long)(gm + 8) * ldc + gn;
                float2 r0, r1;
                r0.x = alpha * c[0]; r0.y = alpha * c[1];
                r1.x = alpha * c[2]; r1.y = alpha * c[3];
                if (beta != 0.f) {
                    float2 p0 = *(float2*)(C + o0);
                    float2 p1 = *(float2*)(C + o1);
                    r0.x += beta * p0.x; r0.y += beta * p0.y;
                    r1.x += beta * p1.x; r1.y += beta * p1.y;
                }
                *(float2*)(C + o0) = r0;
                *(float2*)(C + o1) = r1;
            }
        }
    }
}

// ---------------------------------------------------------------------------
// Compensated-fp32 GEMM (C = A * B^T): TwoProd (fmaf) + Neumaier summation,
// ~exactly-rounded results (error ~2^-45) at fp32 speed. Feeds the top-k
// chain (t1, query) so fp64 rescore inputs match the exact values.
// ---------------------------------------------------------------------------
__global__ __launch_bounds__(256)
void gemm_comp(int M, int N, int Kd,
               const float* __restrict__ A, int lda, long sAb,
               const float* __restrict__ B, int ldb,
               float* __restrict__ C, int ldc, long sCb)
{
    int b = blockIdx.z;
    A += (long)b * sAb;
    C += (long)b * sCb;

    int row0 = blockIdx.y << 6;
    int col0 = blockIdx.x << 6;

    __shared__ float As[8][68];
    __shared__ float Bs[8][68];

    int tid = threadIdx.x;
    int tx = tid & 15, ty = tid >> 4;

    float s_[4][4], c_[4][4];
#pragma unroll
    for (int i = 0; i < 4; i++)
#pragma unroll
        for (int j = 0; j < 4; j++) { s_[i][j] = 0.f; c_[i][j] = 0.f; }

    for (int k0 = 0; k0 < Kd; k0 += 8) {
#pragma unroll
        for (int l = 0; l < 2; l++) {
            int idx = tid + (l << 8);
            int m = idx >> 3, k = idx & 7;
            int gm = row0 + m, gk = k0 + k;
            As[k][m] = (gm < M && gk < Kd) ? A[(long)gm * lda + gk] : 0.f;
            int gn = col0 + m;
            Bs[k][m] = (gn < N && gk < Kd) ? B[(long)gn * ldb + gk] : 0.f;
        }
        __syncthreads();

#pragma unroll
        for (int kk = 0; kk < 8; kk++) {
            float a[4], bb[4];
#pragma unroll
            for (int i = 0; i < 4; i++) a[i]  = As[kk][(ty << 2) + i];
#pragma unroll
            for (int j = 0; j < 4; j++) bb[j] = Bs[kk][(tx << 2) + j];
#pragma unroll
            for (int i = 0; i < 4; i++)
#pragma unroll
                for (int j = 0; j < 4; j++) {
                    float p = a[i] * bb[j];
                    float e = fmaf(a[i], bb[j], -p);       // exact product err
                    float s = s_[i][j];
                    float t = s + p;
                    float zc = (fabsf(s) >= fabsf(p)) ? ((s - t) + p)
                                                      : ((p - t) + s);
                    c_[i][j] += zc + e;
                    s_[i][j] = t;
                }
        }
        __syncthreads();
    }

#pragma unroll
    for (int i = 0; i < 4; i++) {
        int gm = row0 + (ty << 2) + i;
        if (gm >= M) continue;
#pragma unroll
        for (int j = 0; j < 4; j++) {
            int gn = col0 + (tx << 2) + j;
            if (gn >= N) continue;
            C[(long)gm * ldc + gn] = s_[i][j] + c_[i][j];
        }
    }
}

// ---------------------------------------------------------------------------
// Causal row softmax on S[row, :T]; valid cols j <= q (q = row % L).
// ---------------------------------------------------------------------------
__global__ void causal_softmax_k(float* __restrict__ S, int L, int T)
{
    long row = blockIdx.x;
    int q = (int)(row % L);
    float* p = S + row * (long)T;
    int n = q + 1;
    int tid = threadIdx.x;
    __shared__ float red[32];

    float m = -INFINITY;
    for (int j = tid; j < n; j += blockDim.x) m = fmaxf(m, p[j]);
#pragma unroll
    for (int o = 16; o; o >>= 1) m = fmaxf(m, __shfl_xor_sync(0xffffffffu, m, o));
    if ((tid & 31) == 0) red[tid >> 5] = m;
    __syncthreads();
    if (tid < 32) {
        float v = (tid < (int)(blockDim.x >> 5)) ? red[tid] : -INFINITY;
#pragma unroll
        for (int o = 16; o; o >>= 1) v = fmaxf(v, __shfl_xor_sync(0xffffffffu, v, o));
        if (tid == 0) red[0] = v;
    }
    __syncthreads();
    m = red[0];
    __syncthreads();

    float s = 0.f;
    for (int j = tid; j < n; j += blockDim.x) {
        float e = expf(p[j] - m);
        p[j] = e;
        s += e;
    }
#pragma unroll
    for (int o = 16; o; o >>= 1) s += __shfl_xor_sync(0xffffffffu, s, o);
    if ((tid & 31) == 0) red[tid >> 5] = s;
    __syncthreads();
    if (tid < 32) {
        float v = (tid < (int)(blockDim.x >> 5)) ? red[tid] : 0.f;
#pragma unroll
        for (int o = 16; o; o >>= 1) v += __shfl_xor_sync(0xffffffffu, v, o);
        if (tid == 0) red[0] = v;
    }
    __syncthreads();
    float inv = 1.f / red[0];
    for (int j = tid; j < n; j += blockDim.x) p[j] *= inv;
    for (int j = n + tid; j < T; j += blockDim.x) p[j] = 0.f;
}

// ---------------------------------------------------------------------------
// Top-4 with fp64 refinement (stripe top-4 -> serial top-16 -> fp64 rescore
// -> top-4). Tie-break: lower index (matches jax.lax.top_k).
// ---------------------------------------------------------------------------
__global__ __launch_bounds__(256)
void topk4_refine_k(const float* __restrict__ sim,
                    const float* __restrict__ qry,
                    const float* __restrict__ keys,
                    int* __restrict__ out)
{
    long row = blockIdx.x;
    int b   = (int)(row >> 9);
    int tok = (int)(row & (NTOK - 1));
    const float* p = sim + row * (long)NIDX;
    int tid = threadIdx.x;

    float v0 = -INFINITY, v1 = -INFINITY, v2 = -INFINITY, v3 = -INFINITY;
    int   i0 = 0x7fffffff, i1 = 0x7fffffff, i2 = 0x7fffffff, i3 = 0x7fffffff;

    for (int j = tid; j < NIDX; j += 256) {
        float x = p[j];
        if (x > v3 || (x == v3 && j < i3)) {
            if (x > v0 || (x == v0 && j < i0)) {
                v3 = v2; i3 = i2; v2 = v1; i2 = i1; v1 = v0; i1 = i0; v0 = x; i0 = j;
            } else if (x > v1 || (x == v1 && j < i1)) {
                v3 = v2; i3 = i2; v2 = v1; i2 = i1; v1 = x; i1 = j;
            } else if (x > v2 || (x == v2 && j < i2)) {
                v3 = v2; i3 = i2; v2 = x; i2 = j;
            } else {
                v3 = x; i3 = j;
            }
        }
    }

    __shared__ float sv[1024];
    __shared__ int   si[1024];
    sv[tid * 4 + 0] = v0; si[tid * 4 + 0] = i0;
    sv[tid * 4 + 1] = v1; si[tid * 4 + 1] = i1;
    sv[tid * 4 + 2] = v2; si[tid * 4 + 2] = i2;
    sv[tid * 4 + 3] = v3; si[tid * 4 + 3] = i3;
    __syncthreads();

    __shared__ int   cidx[16];
    __shared__ float cval[16];
    if (tid == 0) {
        for (int r = 0; r < 16; r++) {
            float best = -INFINITY; int bid = 0x7fffffff; int bp = -1;
            for (int i = 0; i < 1024; i++) {
                float x = sv[i];
                if (x > best || (x == best && si[i] < bid)) { best = x; bid = si[i]; bp = i; }
            }
            cidx[r] = bid;
            sv[bp] = -INFINITY; si[bp] = 0x7fffffff;
        }
    }
    __syncthreads();

    {
        int warp = tid >> 5, lane = tid & 31;
        int c = (warp << 1) + (lane >> 4);
        int l = lane & 15;
        const float* qrow = qry + ((long)b * SEQ + tok) * IDXD;
        const float* krow = keys + (long)cidx[c] * IDXD;
        double s = 0.0;
        for (int t = l; t < IDXD; t += 16)
            s = fma((double)qrow[t], (double)krow[t], s);
#pragma unroll
        for (int o = 8; o; o >>= 1) s += __shfl_xor_sync(0xffffffffu, s, o, 16);
        if (l == 0) cval[c] = (float)s;
    }
    __syncthreads();

    if (tid == 0) {
        float lv[16]; int li[16];
#pragma unroll
        for (int i = 0; i < 16; i++) { lv[i] = cval[i]; li[i] = cidx[i]; }
        for (int r = 0; r < TOPK; r++) {
            float best = -INFINITY; int bid = 0x7fffffff; int bp = -1;
#pragma unroll
            for (int i = 0; i < 16; i++) {
                float x = lv[i];
                if (x > best || (x == best && li[i] < bid)) { best = x; bid = li[i]; bp = i; }
            }
            out[row * TOPK + r] = bid;
            lv[bp] = -INFINITY; li[bp] = 0x7fffffff;
        }
    }
}

// ---------------------------------------------------------------------------
// Gather adapter K/V rows
// ---------------------------------------------------------------------------
__global__ void gather_k(const int* __restrict__ tidx,
                         const float* __restrict__ keys,
                         const float* __restrict__ vals,
                         float* __restrict__ aK, float* __restrict__ aV)
{
    int blk = blockIdx.x;
    int b = blk >> 11;
    int j = blk & 2047;
    int id = tidx[((b * NTOK + (j >> 2)) << 2) + (j & 3)];
    const float4* ks = (const float4*)(keys + (long)id * IDXD);
    const float4* vs = (const float4*)(vals + (long)id * IDXD);
    float4* dk = (float4*)(aK + (long)blk * IDXD);
    float4* dv = (float4*)(aV + (long)blk * IDXD);
    int t = threadIdx.x;
    dk[t] = ks[t];
    dv[t] = vs[t];
}

// ---------------------------------------------------------------------------
// Host launch
// ---------------------------------------------------------------------------
extern "C" void kernel_launch(void* const* d_in, const int* in_sizes, int n_in,
                              void* d_out, int out_size)
{
    const float* hs    = (const float*)d_in[0];
    const float* Wq    = (const float*)d_in[1];
    const float* Wk    = (const float*)d_in[2];
    const float* Wv    = (const float*)d_in[3];
    const float* Wo    = (const float*)d_in[4];
    const float* q_in  = (const float*)d_in[5];
    const float* q_out = (const float*)d_in[6];
    const float* v_in  = (const float*)d_in[7];
    const float* v_out = (const float*)d_in[8];
    const float* ikeys = (const float*)d_in[9];
    const float* ivals = (const float*)d_in[10];
    float* out = (float*)d_out;

    void* p;
    cudaGetSymbolAddress(&p, g_Q);      float* Qb   = (float*)p;
    cudaGetSymbolAddress(&p, g_K);      float* Kb   = (float*)p;
    cudaGetSymbolAddress(&p, g_V);      float* Vb   = (float*)p;
    cudaGetSymbolAddress(&p, g_attn);   float* Ab   = (float*)p;
    cudaGetSymbolAddress(&p, g_scores); float* Sb   = (float*)p;
    cudaGetSymbolAddress(&p, g_t1);     float* t1   = (float*)p;
    cudaGetSymbolAddress(&p, g_query);  float* qry  = (float*)p;
    cudaGetSymbolAddress(&p, g_sim);    float* simb = (float*)p;
    cudaGetSymbolAddress(&p, g_topidx); int*   topi = (int*)p;
    cudaGetSymbolAddress(&p, g_aK);     float* aK   = (float*)p;
    cudaGetSymbolAddress(&p, g_aV);     float* aV   = (float*)p;
    cudaGetSymbolAddress(&p, g_sc2);    float* sc2  = (float*)p;
    cudaGetSymbolAddress(&p, g_mome);   float* mome = (float*)p;
    cudaGetSymbolAddress(&p, g_t2);     float* t2   = (float*)p;

    const int MS = BATCH * SEQ;                        // 8192
    const float scale_base = 1.0f / sqrtf((float)HD);
    const float scale_adpt = 1.0f / sqrtf((float)IDXD);
    dim3 blk(256);

    // 1) Q/K/V projections: [8192,2048] = hs @ W^T
    gemm_mma<true><<<dim3(HID / 128, MS / 128, 1), blk>>>(MS, HID, HID, 1.f, 0.f,
        hs, HID, 0, 0, Wq, HID, 0, 0, Qb, HID, 0, 0, 1, 0, 0);
    gemm_mma<true><<<dim3(HID / 128, MS / 128, 1), blk>>>(MS, HID, HID, 1.f, 0.f,
        hs, HID, 0, 0, Wk, HID, 0, 0, Kb, HID, 0, 0, 1, 0, 0);
    gemm_mma<true><<<dim3(HID / 128, MS / 128, 1), blk>>>(MS, HID, HID, 1.f, 0.f,
        hs, HID, 0, 0, Wv, HID, 0, 0, Vb, HID, 0, 0, 1, 0, 0);

    // 2) base scores (batched over b,h), causal tile-skip
    gemm_mma<true><<<dim3(SEQ / 128, SEQ / 128, BATCH * NHEAD), blk>>>(
        SEQ, SEQ, HD, scale_base, 0.f,
        Qb, HID, (long)SEQ * HID, HD,
        Kb, HID, (long)SEQ * HID, HD,
        Sb, SEQ, (long)NHEAD * SEQ * SEQ, (long)SEQ * SEQ,
        NHEAD, 1, 0);

    // 3) causal softmax
    causal_softmax_k<<<BATCH * NHEAD * SEQ, 256>>>(Sb, SEQ, SEQ);

    // 4) AV: attn_out = P @ V (NN, causal K-limit)
    gemm_mma<false><<<dim3(1, SEQ / 128, BATCH * NHEAD), blk>>>(
        SEQ, HD, SEQ, 1.f, 0.f,
        Sb, SEQ, (long)NHEAD * SEQ * SEQ, (long)SEQ * SEQ,
        Vb, HID, (long)SEQ * HID, HD,
        Ab, HID, (long)SEQ * HID, HD,
        NHEAD, 0, 1);

    // 5) out = attn_out @ Wo^T
    gemm_mma<true><<<dim3(HID / 128, MS / 128, 1), blk>>>(MS, HID, HID, 1.f, 0.f,
        Ab, HID, 0, 0, Wo, HID, 0, 0, out, HID, 0, 0, 1, 0, 0);

    // 6) t1 = hs @ q_in^T   [8192,64]  (compensated fp32: feeds top-k chain)
    gemm_comp<<<dim3(RNK / 64, MS / 64, 1), blk>>>(MS, RNK, HID,
        hs, HID, 0, q_in, HID, t1, RNK, 0);

    // 7) query = t1 @ q_out^T   [8192,512]  (compensated fp32)
    gemm_comp<<<dim3(IDXD / 64, MS / 64, 1), blk>>>(MS, IDXD, RNK,
        t1, RNK, 0, q_out, RNK, qry, IDXD, 0);

    // 8) sim = query[:512 tokens/batch] @ index_keys^T  (bf16x3, batched)
    gemm_mma<true><<<dim3(NIDX / 128, NTOK / 128, BATCH), blk>>>(
        NTOK, NIDX, IDXD, 1.f, 0.f,
        qry, IDXD, (long)SEQ * IDXD, 0,
        ikeys, IDXD, 0, 0,
        simb, NIDX, (long)NTOK * NIDX, 0,
        1, 0, 0);

    // 9) top-4 per row with fp64 candidate rescoring
    topk4_refine_k<<<BATCH * NTOK, 256>>>(simb, qry, ikeys, topi);

    // 10) gather adapter K/V
    gather_k<<<BATCH * SEQ, 128>>>(topi, ikeys, ivals, aK, aV);

    // 11) adapter scores = query @ aK^T (batched over b, causal tile-skip)
    gemm_mma<true><<<dim3(SEQ / 128, SEQ / 128, BATCH), blk>>>(
        SEQ, SEQ, IDXD, scale_adpt, 0.f,
        qry, IDXD, (long)SEQ * IDXD, 0,
        aK, IDXD, (long)SEQ * IDXD, 0,
        sc2, SEQ, (long)SEQ * SEQ, 0,
        1, 1, 0);

    // 12) causal softmax
    causal_softmax_k<<<BATCH * SEQ, 256>>>(sc2, SEQ, SEQ);

    // 13) mome_attn = P @ aV (NN, causal K-limit)
    gemm_mma<false><<<dim3(IDXD / 128, SEQ / 128, BATCH), blk>>>(
        SEQ, IDXD, SEQ, 1.f, 0.f,
        sc2, SEQ, (long)SEQ * SEQ, 0,
        aV, IDXD, (long)SEQ * IDXD, 0,
        mome, IDXD, (long)SEQ * IDXD, 0,
        1, 0, 1);

    // 14) t2 = mome @ v_in^T   [8192,64]
    gemm_mma<true><<<dim3(1, MS / 128, 1), blk>>>(MS, RNK, IDXD, 1.f, 0.f,
        mome, IDXD, 0, 0, v_in, IDXD, 0, 0, t2, RNK, 0, 0, 1, 0, 0);

    // 15) out += R * (t2 @ v_out^T)
    gemm_mma<true><<<dim3(HID / 128, MS / 128, 1), blk>>>(MS, HID, RNK,
        (float)RNK, 1.f,
        t2, RNK, 0, 0, v_out, RNK, 0, 0, out, HID, 0, 0, 1, 0, 0);
}

// round 17
// speedup vs baseline: 2.9607x; 1.3387x over previous
#include <cuda_runtime.h>
#include <cuda_bf16.h>
#include <math.h>

// ---------------------------------------------------------------------------
// Problem constants
// ---------------------------------------------------------------------------
#define BATCH 4
#define SEQ   2048
#define HID   2048
#define NHEAD 16
#define HD    128
#define RNK   64
#define IDXD  512
#define NIDX  65536
#define TOPK  4
#define NTOK  512          // only first 512 tokens/batch ever attended in adapter

// ---------------------------------------------------------------------------
// Scratch (device globals; no allocation allowed)
// ---------------------------------------------------------------------------
__device__ float g_Q[(size_t)BATCH * SEQ * HID];
__device__ float g_K[(size_t)BATCH * SEQ * HID];
__device__ float g_V[(size_t)BATCH * SEQ * HID];
__device__ float g_attn[(size_t)BATCH * SEQ * HID];
__device__ float g_scores[(size_t)BATCH * NHEAD * SEQ * SEQ];   // 1.07 GB
__device__ float g_t1[(size_t)BATCH * SEQ * RNK];
__device__ float g_query[(size_t)BATCH * SEQ * IDXD];
__device__ float g_sim[(size_t)BATCH * NTOK * NIDX];            // 537 MB (fp32)
__device__ int   g_topidx[BATCH * NTOK * TOPK];
__device__ float g_aK[(size_t)BATCH * SEQ * IDXD];
__device__ float g_aV[(size_t)BATCH * SEQ * IDXD];
__device__ float g_sc2[(size_t)BATCH * SEQ * SEQ];
__device__ float g_mome[(size_t)BATCH * SEQ * IDXD];
__device__ float g_t2[(size_t)BATCH * SEQ * RNK];

// ---------------------------------------------------------------------------
// Streams / events for DAG concurrency (host-side resources only; created at
// static-init time, before any harness activity or capture).
// ---------------------------------------------------------------------------
struct StreamSet {
    cudaStream_t s1, s2, s3;
    cudaEvent_t evf, ev1, ev2, ev3;
    StreamSet() {
        cudaStreamCreateWithFlags(&s1, cudaStreamNonBlocking);
        cudaStreamCreateWithFlags(&s2, cudaStreamNonBlocking);
        cudaStreamCreateWithFlags(&s3, cudaStreamNonBlocking);
        cudaEventCreateWithFlags(&evf, cudaEventDisableTiming);
        cudaEventCreateWithFlags(&ev1, cudaEventDisableTiming);
        cudaEventCreateWithFlags(&ev2, cudaEventDisableTiming);
        cudaEventCreateWithFlags(&ev3, cudaEventDisableTiming);
    }
};
static StreamSet g_ss;

// ---------------------------------------------------------------------------
// bf16x4 helpers (3 cross terms kept; a1*b1 ~2^-18 dropped)
// ---------------------------------------------------------------------------
__device__ __forceinline__ unsigned pack_bf2(float x, float y)
{
    union { __nv_bfloat162 h; unsigned u; } cv;
    cv.h = __floats2bfloat162_rn(x, y);
    return cv.u;
}

__device__ __forceinline__ void bsplit(float v, float& hi, float& lo)
{
    __nv_bfloat16 h = __float2bfloat16_rn(v);
    hi = __bfloat162float(h);
    lo = v - hi;
}

__device__ __forceinline__ void mma_bf16(float* c, const unsigned* a, const unsigned* b)
{
    asm volatile(
        "mma.sync.aligned.m16n8k16.row.col.f32.bf16.bf16.f32 "
        "{%0,%1,%2,%3}, {%4,%5,%6,%7}, {%8,%9}, {%0,%1,%2,%3};"
        : "+f"(c[0]), "+f"(c[1]), "+f"(c[2]), "+f"(c[3])
        : "r"(a[0]), "r"(a[1]), "r"(a[2]), "r"(a[3]),
          "r"(b[0]), "r"(b[1]));
}

// split a float4 (k..k+3 of one row) and store hi/lo bf16x2 pairs into tile
__device__ __forceinline__ void st_split4(uint2* S0, uint2* S1, float4 v, int id)
{
    int m = id >> 2, kk = (id & 3) << 2;
    float h0, l0, h1, l1, h2, l2, h3, l3;
    bsplit(v.x, h0, l0); bsplit(v.y, h1, l1);
    bsplit(v.z, h2, l2); bsplit(v.w, h3, l3);
    int p0 = (kk & 7) >> 1;
    int hf = (kk >> 3) & 1;
    unsigned* W0 = (unsigned*)S0;
    unsigned* W1 = (unsigned*)S1;
    int base = (m << 2) + p0;
    W0[(base << 1) + hf]       = pack_bf2(h0, h1);
    W0[((base + 1) << 1) + hf] = pack_bf2(h2, h3);
    W1[(base << 1) + hf]       = pack_bf2(l0, l1);
    W1[((base + 1) << 1) + hf] = pack_bf2(l2, l3);
}

// ---------------------------------------------------------------------------
// Tensor-core GEMM (bf16x3, ~fp32 accuracy), double-buffered smem:
//   C = alpha * A * op(B) + beta * C
//   A: [M, K] row-major. TB=true: B [N,K] -> C = A B^T; TB=false: B [K,N].
// Requirements: M % 128 == 0, K % 16 == 0, N % 8 == 0 (TB=false: N % 128 == 0).
// One barrier per k-tile; tile k+1's LDGs issued during tile k's MMA.
// ---------------------------------------------------------------------------
template<bool TB>
__global__ __launch_bounds__(256, 2)
void gemm_mma(int M, int N, int Kd, float alpha, float beta,
              const float* __restrict__ A, int lda, long sAb, long sAh,
              const float* __restrict__ B, int ldb, long sBb, long sBh,
              float* __restrict__ C, int ldc, long sCb, long sCh,
              int nh, int causal_skip, int k_limit)
{
    int z  = blockIdx.z;
    int bb = z / nh, hh = z - bb * nh;
    A += (long)bb * sAb + (long)hh * sAh;
    B += (long)bb * sBb + (long)hh * sBh;
    C += (long)bb * sCb + (long)hh * sCh;

    int row0 = blockIdx.y << 7;
    int col0 = blockIdx.x << 7;
    if (causal_skip && col0 > row0 + 127) return;

    int kEff = Kd;
    if (k_limit) { int lim = row0 + 128; if (lim < kEff) kEff = lim; }
    int nk = kEff >> 4;                       // k-tiles (K % 16 == 0)

    __shared__ uint2 A0s[2][512], A1s[2][512];   // [buf][row*4+slot]
    __shared__ uint2 B0s[2][512], B1s[2][512];   // 32 KB total

    int tid  = threadIdx.x;
    int warp = tid >> 5, lane = tid & 31;
    int wm = warp & 1;          // m offset 0/64
    int wn = warp >> 1;         // n offset 0/32/64/96
    int grp = lane >> 2;        // 0..7
    int tig = lane & 3;         // 0..3

    // hoisted fragment addresses (uint2 indices)
    int aoff[4][2], boff[4];
#pragma unroll
    for (int i = 0; i < 4; i++) {
        int r = (wm << 6) + (i << 4) + grp;
        aoff[i][0] = r * 4 + tig;
        aoff[i][1] = (r + 8) * 4 + tig;
    }
#pragma unroll
    for (int j = 0; j < 4; j++) {
        int n = (wn << 5) + (j << 3) + grp;
        boff[j] = n * 4 + tig;
    }

    float acc[16][4];
#pragma unroll
    for (int f = 0; f < 16; f++)
#pragma unroll
        for (int r = 0; r < 4; r++) acc[f][r] = 0.f;

    // ---- prefetch registers ----
    float4 pa0, pa1;
    float4 pbv0, pbv1;          // TB=true
    float  pbs[8];              // TB=false

    // A addressing (fixed per thread)
    int a_m0 = (tid << 1) >> 2,        a_k0 = (((tid << 1) & 3) << 2);
    int a_m1 = ((tid << 1) + 1) >> 2,  a_k1 = ((((tid << 1) + 1) & 3) << 2);

    auto ldA = [&](int k0) {
        pa0 = *(const float4*)(A + (long)(row0 + a_m0) * lda + (k0 + a_k0));
        pa1 = *(const float4*)(A + (long)(row0 + a_m1) * lda + (k0 + a_k1));
    };
    auto stA = [&](int buf) {
        st_split4(A0s[buf], A1s[buf], pa0, (tid << 1));
        st_split4(A0s[buf], A1s[buf], pa1, (tid << 1) + 1);
    };
    auto ldB = [&](int k0) {
        if (TB) {
            int gn0 = col0 + a_m0, gn1 = col0 + a_m1;
            pbv0 = (gn0 < N) ? *(const float4*)(B + (long)gn0 * ldb + (k0 + a_k0))
                             : make_float4(0.f, 0.f, 0.f, 0.f);
            pbv1 = (gn1 < N) ? *(const float4*)(B + (long)gn1 * ldb + (k0 + a_k1))
                             : make_float4(0.f, 0.f, 0.f, 0.f);
        } else {
#pragma unroll
            for (int s = 0; s < 8; s++) {
                int id = (s << 8) + tid;
                int kk = id >> 7, n = id & 127;
                pbs[s] = B[(long)(k0 + kk) * ldb + (col0 + n)];
            }
        }
    };
    auto stB = [&](int buf) {
        if (TB) {
            st_split4(B0s[buf], B1s[buf], pbv0, (tid << 1));
            st_split4(B0s[buf], B1s[buf], pbv1, (tid << 1) + 1);
        } else {
            unsigned short* B0h = (unsigned short*)B0s[buf];
            unsigned short* B1h = (unsigned short*)B1s[buf];
#pragma unroll
            for (int s = 0; s < 8; s++) {
                int id = (s << 8) + tid;
                int kk = id >> 7, n = id & 127;
                float hi, lo;
                bsplit(pbs[s], hi, lo);
                int p  = (kk & 7) >> 1;
                int hf = (kk >> 3) & 1;
                int e  = kk & 1;
                int idx = ((((n << 2) + p) << 1) + hf) * 2 + e;
                union { __nv_bfloat16 b; unsigned short u; } c0, c1;
                c0.b = __float2bfloat16_rn(hi);
                c1.b = __float2bfloat16_rn(lo);
                B0h[idx] = c0.u;
                B1h[idx] = c1.u;
            }
        }
    };

    // prologue: fill buffer 0
    ldA(0); ldB(0);
    stA(0); stB(0);
    int cur = 0;

    for (int t = 0; t < nk; t++) {
        __syncthreads();                    // buf[cur] visible to all
        bool pf = (t + 1 < nk);
        if (pf) { ldA((t + 1) << 4); ldB((t + 1) << 4); }

        // B fragments (both splits): 8 x LDS.64
        unsigned b0f[4][2], b1f[4][2];
#pragma unroll
        for (int j = 0; j < 4; j++) {
            uint2 v0 = B0s[cur][boff[j]];
            uint2 v1 = B1s[cur][boff[j]];
            b0f[j][0] = v0.x; b0f[j][1] = v0.y;
            b1f[j][0] = v1.x; b1f[j][1] = v1.y;
        }
        {   // a0 passes: a0*b0, a0*b1
            unsigned af[4][4];
#pragma unroll
            for (int i = 0; i < 4; i++) {
                uint2 u0 = A0s[cur][aoff[i][0]];
                uint2 u1 = A0s[cur][aoff[i][1]];
                af[i][0] = u0.x; af[i][1] = u1.x; af[i][2] = u0.y; af[i][3] = u1.y;
            }
#pragma unroll
            for (int j = 0; j < 4; j++)
#pragma unroll
                for (int i = 0; i < 4; i++) mma_bf16(acc[i * 4 + j], af[i], b0f[j]);
#pragma unroll
            for (int j = 0; j < 4; j++)
#pragma unroll
                for (int i = 0; i < 4; i++) mma_bf16(acc[i * 4 + j], af[i], b1f[j]);
        }
        {   // a1 pass: a1*b0   (a1*b1 ~2^-18 dropped)
            unsigned af[4][4];
#pragma unroll
            for (int i = 0; i < 4; i++) {
                uint2 u0 = A1s[cur][aoff[i][0]];
                uint2 u1 = A1s[cur][aoff[i][1]];
                af[i][0] = u0.x; af[i][1] = u1.x; af[i][2] = u0.y; af[i][3] = u1.y;
            }
#pragma unroll
            for (int j = 0; j < 4; j++)
#pragma unroll
                for (int i = 0; i < 4; i++) mma_bf16(acc[i * 4 + j], af[i], b0f[j]);
        }

        if (pf) { stA(cur ^ 1); stB(cur ^ 1); }
        cur ^= 1;
    }

    // ---- epilogue ----
#pragma unroll
    for (int i = 0; i < 4; i++) {
#pragma unroll
        for (int j = 0; j < 4; j++) {
            float* c = acc[i * 4 + j];
            int gm = row0 + (wm << 6) + (i << 4) + grp;
            int gn = col0 + (wn << 5) + (j << 3) + (tig << 1);
            if (gn < N) {     // N % 8 == 0 -> gn+1 < N too
                long o0 = (long)gm * ldc + gn;
                long o1 = (long)(gm + 8) * ldc + gn;
                float2 r0, r1;
                r0.x = alpha * c[0]; r0.y = alpha * c[1];
                r1.x = alpha * c[2]; r1.y = alpha * c[3];
                if (beta != 0.f) {
                    float2 p0 = *(float2*)(C + o0);
                    float2 p1 = *(float2*)(C + o1);
                    r0.x += beta * p0.x; r0.y += beta * p0.y;
                    r1.x += beta * p1.x; r1.y += beta * p1.y;
                }
                *(float2*)(C + o0) = r0;
                *(float2*)(C + o1) = r1;
            }
        }
    }
}

// ---------------------------------------------------------------------------
// Compensated-fp32 GEMM (C = A * B^T): TwoProd (fmaf) + Neumaier summation,
// ~exactly-rounded results at fp32 speed. Feeds the top-k chain (t1, query).
// ---------------------------------------------------------------------------
__global__ __launch_bounds__(256)
void gemm_comp(int M, int N, int Kd,
               const float* __restrict__ A, int lda, long sAb,
               const float* __restrict__ B, int ldb,
               float* __restrict__ C, int ldc, long sCb)
{
    int b = blockIdx.z;
    A += (long)b * sAb;
    C += (long)b * sCb;

    int row0 = blockIdx.y << 6;
    int col0 = blockIdx.x << 6;

    __shared__ float As[8][68];
    __shared__ float Bs[8][68];

    int tid = threadIdx.x;
    int tx = tid & 15, ty = tid >> 4;

    float s_[4][4], c_[4][4];
#pragma unroll
    for (int i = 0; i < 4; i++)
#pragma unroll
        for (int j = 0; j < 4; j++) { s_[i][j] = 0.f; c_[i][j] = 0.f; }

    for (int k0 = 0; k0 < Kd; k0 += 8) {
#pragma unroll
        for (int l = 0; l < 2; l++) {
            int idx = tid + (l << 8);
            int m = idx >> 3, k = idx & 7;
            int gm = row0 + m, gk = k0 + k;
            As[k][m] = (gm < M && gk < Kd) ? A[(long)gm * lda + gk] : 0.f;
            int gn = col0 + m;
            Bs[k][m] = (gn < N && gk < Kd) ? B[(long)gn * ldb + gk] : 0.f;
        }
        __syncthreads();

#pragma unroll
        for (int kk = 0; kk < 8; kk++) {
            float a[4], bb[4];
#pragma unroll
            for (int i = 0; i < 4; i++) a[i]  = As[kk][(ty << 2) + i];
#pragma unroll
            for (int j = 0; j < 4; j++) bb[j] = Bs[kk][(tx << 2) + j];
#pragma unroll
            for (int i = 0; i < 4; i++)
#pragma unroll
                for (int j = 0; j < 4; j++) {
                    float p = a[i] * bb[j];
                    float e = fmaf(a[i], bb[j], -p);       // exact product err
                    float s = s_[i][j];
                    float t = s + p;
                    float zc = (fabsf(s) >= fabsf(p)) ? ((s - t) + p)
                                                      : ((p - t) + s);
                    c_[i][j] += zc + e;
                    s_[i][j] = t;
                }
        }
        __syncthreads();
    }

#pragma unroll
    for (int i = 0; i < 4; i++) {
        int gm = row0 + (ty << 2) + i;
        if (gm >= M) continue;
#pragma unroll
        for (int j = 0; j < 4; j++) {
            int gn = col0 + (tx << 2) + j;
            if (gn >= N) continue;
            C[(long)gm * ldc + gn] = s_[i][j] + c_[i][j];
        }
    }
}

// ---------------------------------------------------------------------------
// Causal row softmax on S[row, :T]; valid cols j <= q (q = row % L).
// ---------------------------------------------------------------------------
__global__ void causal_softmax_k(float* __restrict__ S, int L, int T)
{
    long row = blockIdx.x;
    int q = (int)(row % L);
    float* p = S + row * (long)T;
    int n = q + 1;
    int tid = threadIdx.x;
    __shared__ float red[32];

    float m = -INFINITY;
    for (int j = tid; j < n; j += blockDim.x) m = fmaxf(m, p[j]);
#pragma unroll
    for (int o = 16; o; o >>= 1) m = fmaxf(m, __shfl_xor_sync(0xffffffffu, m, o));
    if ((tid & 31) == 0) red[tid >> 5] = m;
    __syncthreads();
    if (tid < 32) {
        float v = (tid < (int)(blockDim.x >> 5)) ? red[tid] : -INFINITY;
#pragma unroll
        for (int o = 16; o; o >>= 1) v = fmaxf(v, __shfl_xor_sync(0xffffffffu, v, o));
        if (tid == 0) red[0] = v;
    }
    __syncthreads();
    m = red[0];
    __syncthreads();

    float s = 0.f;
    for (int j = tid; j < n; j += blockDim.x) {
        float e = expf(p[j] - m);
        p[j] = e;
        s += e;
    }
#pragma unroll
    for (int o = 16; o; o >>= 1) s += __shfl_xor_sync(0xffffffffu, s, o);
    if ((tid & 31) == 0) red[tid >> 5] = s;
    __syncthreads();
    if (tid < 32) {
        float v = (tid < (int)(blockDim.x >> 5)) ? red[tid] : 0.f;
#pragma unroll
        for (int o = 16; o; o >>= 1) v += __shfl_xor_sync(0xffffffffu, v, o);
        if (tid == 0) red[0] = v;
    }
    __syncthreads();
    float inv = 1.f / red[0];
    for (int j = tid; j < n; j += blockDim.x) p[j] *= inv;
    for (int j = n + tid; j < T; j += blockDim.x) p[j] = 0.f;
}

// ---------------------------------------------------------------------------
// Top-4 with fp64 refinement (stripe top-4 -> block-parallel top-16 ->
// fp64 rescore -> top-4). Tie-break: lower index (matches jax.lax.top_k).
// ---------------------------------------------------------------------------
__global__ __launch_bounds__(256)
void topk4_refine_k(const float* __restrict__ sim,
                    const float* __restrict__ qry,
                    const float* __restrict__ keys,
                    int* __restrict__ out)
{
    long row = blockIdx.x;
    int b   = (int)(row >> 9);
    int tok = (int)(row & (NTOK - 1));
    const float* p = sim + row * (long)NIDX;
    int tid = threadIdx.x;

    float v0 = -INFINITY, v1 = -INFINITY, v2 = -INFINITY, v3 = -INFINITY;
    int   i0 = 0x7fffffff, i1 = 0x7fffffff, i2 = 0x7fffffff, i3 = 0x7fffffff;

    for (int j = tid; j < NIDX; j += 256) {
        float x = p[j];
        if (x > v3 || (x == v3 && j < i3)) {
            if (x > v0 || (x == v0 && j < i0)) {
                v3 = v2; i3 = i2; v2 = v1; i2 = i1; v1 = v0; i1 = i0; v0 = x; i0 = j;
            } else if (x > v1 || (x == v1 && j < i1)) {
                v3 = v2; i3 = i2; v2 = v1; i2 = i1; v1 = x; i1 = j;
            } else if (x > v2 || (x == v2 && j < i2)) {
                v3 = v2; i3 = i2; v2 = x; i2 = j;
            } else {
                v3 = x; i3 = j;
            }
        }
    }

    __shared__ float sv[1024];
    __shared__ int   si[1024];
    sv[tid * 4 + 0] = v0; si[tid * 4 + 0] = i0;
    sv[tid * 4 + 1] = v1; si[tid * 4 + 1] = i1;
    sv[tid * 4 + 2] = v2; si[tid * 4 + 2] = i2;
    sv[tid * 4 + 3] = v3; si[tid * 4 + 3] = i3;
    __syncthreads();

    // block-parallel top-16 extraction (argmax with (val desc, idx asc) order)
    __shared__ int   cidx[16];
    __shared__ float cval[16];
    __shared__ float rbv[8];
    __shared__ int   rbi[8], rbp[8];

    for (int r = 0; r < 16; r++) {
        float bv = -INFINITY; int bi = 0x7fffffff; int bp = 0;
        for (int i = tid; i < 1024; i += 256) {
            float x = sv[i]; int ii = si[i];
            if (x > bv || (x == bv && ii < bi)) { bv = x; bi = ii; bp = i; }
        }
#pragma unroll
        for (int o = 16; o; o >>= 1) {
            float ov = __shfl_down_sync(0xffffffffu, bv, o);
            int   oi = __shfl_down_sync(0xffffffffu, bi, o);
            int   op = __shfl_down_sync(0xffffffffu, bp, o);
            if (ov > bv || (ov == bv && oi < bi)) { bv = ov; bi = oi; bp = op; }
        }
        if ((tid & 31) == 0) { rbv[tid >> 5] = bv; rbi[tid >> 5] = bi; rbp[tid >> 5] = bp; }
        __syncthreads();
        if (tid == 0) {
            float fv = rbv[0]; int fi = rbi[0]; int fp = rbp[0];
#pragma unroll
            for (int w = 1; w < 8; w++)
                if (rbv[w] > fv || (rbv[w] == fv && rbi[w] < fi)) {
                    fv = rbv[w]; fi = rbi[w]; fp = rbp[w];
                }
            cidx[r] = fi;
            sv[fp] = -INFINITY; si[fp] = 0x7fffffff;
        }
        __syncthreads();
    }

    // fp64 rescore of 16 candidates (half-warp per candidate)
    {
        int warp = tid >> 5, lane = tid & 31;
        int c = (warp << 1) + (lane >> 4);
        int l = lane & 15;
        const float* qrow = qry + ((long)b * SEQ + tok) * IDXD;
        const float* krow = keys + (long)cidx[c] * IDXD;
        double s = 0.0;
        for (int t = l; t < IDXD; t += 16)
            s = fma((double)qrow[t], (double)krow[t], s);
#pragma unroll
        for (int o = 8; o; o >>= 1) s += __shfl_xor_sync(0xffffffffu, s, o, 16);
        if (l == 0) cval[c] = (float)s;
    }
    __syncthreads();

    if (tid == 0) {
        float lv[16]; int li[16];
#pragma unroll
        for (int i = 0; i < 16; i++) { lv[i] = cval[i]; li[i] = cidx[i]; }
        for (int r = 0; r < TOPK; r++) {
            float best = -INFINITY; int bid = 0x7fffffff; int bp = -1;
#pragma unroll
            for (int i = 0; i < 16; i++) {
                float x = lv[i];
                if (x > best || (x == best && li[i] < bid)) { best = x; bid = li[i]; bp = i; }
            }
            out[row * TOPK + r] = bid;
            lv[bp] = -INFINITY; li[bp] = 0x7fffffff;
        }
    }
}

// ---------------------------------------------------------------------------
// Gather adapter K/V rows
// ---------------------------------------------------------------------------
__global__ void gather_k(const int* __restrict__ tidx,
                         const float* __restrict__ keys,
                         const float* __restrict__ vals,
                         float* __restrict__ aK, float* __restrict__ aV)
{
    int blk = blockIdx.x;
    int b = blk >> 11;
    int j = blk & 2047;
    int id = tidx[((b * NTOK + (j >> 2)) << 2) + (j & 3)];
    const float4* ks = (const float4*)(keys + (long)id * IDXD);
    const float4* vs = (const float4*)(vals + (long)id * IDXD);
    float4* dk = (float4*)(aK + (long)blk * IDXD);
    float4* dv = (float4*)(aV + (long)blk * IDXD);
    int t = threadIdx.x;
    dk[t] = ks[t];
    dv[t] = vs[t];
}

// ---------------------------------------------------------------------------
// Host launch — forked DAG across streams:
//   stream0: Qproj -> scores -> softmax -> AV -> Wo -> (join) step15
//   s1:      Kproj                 (scores waits ev1)
//   s2:      Vproj                 (AV waits ev2)
//   s3:      t1 -> query -> sim -> topk -> gather -> sc2 -> softmax -> mome
//            -> t2                 (step15 waits ev3)
// ---------------------------------------------------------------------------
extern "C" void kernel_launch(void* const* d_in, const int* in_sizes, int n_in,
                              void* d_out, int out_size)
{
    const float* hs    = (const float*)d_in[0];
    const float* Wq    = (const float*)d_in[1];
    const float* Wk    = (const float*)d_in[2];
    const float* Wv    = (const float*)d_in[3];
    const float* Wo    = (const float*)d_in[4];
    const float* q_in  = (const float*)d_in[5];
    const float* q_out = (const float*)d_in[6];
    const float* v_in  = (const float*)d_in[7];
    const float* v_out = (const float*)d_in[8];
    const float* ikeys = (const float*)d_in[9];
    const float* ivals = (const float*)d_in[10];
    float* out = (float*)d_out;

    void* p;
    cudaGetSymbolAddress(&p, g_Q);      float* Qb   = (float*)p;
    cudaGetSymbolAddress(&p, g_K);      float* Kb   = (float*)p;
    cudaGetSymbolAddress(&p, g_V);      float* Vb   = (float*)p;
    cudaGetSymbolAddress(&p, g_attn);   float* Ab   = (float*)p;
    cudaGetSymbolAddress(&p, g_scores); float* Sb   = (float*)p;
    cudaGetSymbolAddress(&p, g_t1);     float* t1   = (float*)p;
    cudaGetSymbolAddress(&p, g_query);  float* qry  = (float*)p;
    cudaGetSymbolAddress(&p, g_sim);    float* simb = (float*)p;
    cudaGetSymbolAddress(&p, g_topidx); int*   topi = (int*)p;
    cudaGetSymbolAddress(&p, g_aK);     float* aK   = (float*)p;
    cudaGetSymbolAddress(&p, g_aV);     float* aV   = (float*)p;
    cudaGetSymbolAddress(&p, g_sc2);    float* sc2  = (float*)p;
    cudaGetSymbolAddress(&p, g_mome);   float* mome = (float*)p;
    cudaGetSymbolAddress(&p, g_t2);     float* t2   = (float*)p;

    const int MS = BATCH * SEQ;                        // 8192
    const float scale_base = 1.0f / sqrtf((float)HD);
    const float scale_adpt = 1.0f / sqrtf((float)IDXD);
    dim3 blk(256);

    cudaStream_t s1 = g_ss.s1, s2 = g_ss.s2, s3 = g_ss.s3;

    // ---- fork ----
    cudaEventRecord(g_ss.evf, 0);
    cudaStreamWaitEvent(s1, g_ss.evf, 0);
    cudaStreamWaitEvent(s2, g_ss.evf, 0);
    cudaStreamWaitEvent(s3, g_ss.evf, 0);

    // stream0: Q projection
    gemm_mma<true><<<dim3(HID / 128, MS / 128, 1), blk, 0, 0>>>(MS, HID, HID,
        1.f, 0.f, hs, HID, 0, 0, Wq, HID, 0, 0, Qb, HID, 0, 0, 1, 0, 0);

    // s1: K projection
    gemm_mma<true><<<dim3(HID / 128, MS / 128, 1), blk, 0, s1>>>(MS, HID, HID,
        1.f, 0.f, hs, HID, 0, 0, Wk, HID, 0, 0, Kb, HID, 0, 0, 1, 0, 0);
    cudaEventRecord(g_ss.ev1, s1);

    // s2: V projection
    gemm_mma<true><<<dim3(HID / 128, MS / 128, 1), blk, 0, s2>>>(MS, HID, HID,
        1.f, 0.f, hs, HID, 0, 0, Wv, HID, 0, 0, Vb, HID, 0, 0, 1, 0, 0);
    cudaEventRecord(g_ss.ev2, s2);

    // s3: full adapter chain
    gemm_comp<<<dim3(RNK / 64, MS / 64, 1), blk, 0, s3>>>(MS, RNK, HID,
        hs, HID, 0, q_in, HID, t1, RNK, 0);
    gemm_comp<<<dim3(IDXD / 64, MS / 64, 1), blk, 0, s3>>>(MS, IDXD, RNK,
        t1, RNK, 0, q_out, RNK, qry, IDXD, 0);
    gemm_mma<true><<<dim3(NIDX / 128, NTOK / 128, BATCH), blk, 0, s3>>>(
        NTOK, NIDX, IDXD, 1.f, 0.f,
        qry, IDXD, (long)SEQ * IDXD, 0,
        ikeys, IDXD, 0, 0,
        simb, NIDX, (long)NTOK * NIDX, 0,
        1, 0, 0);
    topk4_refine_k<<<BATCH * NTOK, 256, 0, s3>>>(simb, qry, ikeys, topi);
    gather_k<<<BATCH * SEQ, 128, 0, s3>>>(topi, ikeys, ivals, aK, aV);
    gemm_mma<true><<<dim3(SEQ / 128, SEQ / 128, BATCH), blk, 0, s3>>>(
        SEQ, SEQ, IDXD, scale_adpt, 0.f,
        qry, IDXD, (long)SEQ * IDXD, 0,
        aK, IDXD, (long)SEQ * IDXD, 0,
        sc2, SEQ, (long)SEQ * SEQ, 0,
        1, 1, 0);
    causal_softmax_k<<<BATCH * SEQ, 256, 0, s3>>>(sc2, SEQ, SEQ);
    gemm_mma<false><<<dim3(IDXD / 128, SEQ / 128, BATCH), blk, 0, s3>>>(
        SEQ, IDXD, SEQ, 1.f, 0.f,
        sc2, SEQ, (long)SEQ * SEQ, 0,
        aV, IDXD, (long)SEQ * IDXD, 0,
        mome, IDXD, (long)SEQ * IDXD, 0,
        1, 0, 1);
    gemm_mma<true><<<dim3(1, MS / 128, 1), blk, 0, s3>>>(MS, RNK, IDXD,
        1.f, 0.f, mome, IDXD, 0, 0, v_in, IDXD, 0, 0, t2, RNK, 0, 0, 1, 0, 0);
    cudaEventRecord(g_ss.ev3, s3);

    // stream0: scores (needs Q + K)
    cudaStreamWaitEvent(0, g_ss.ev1, 0);
    gemm_mma<true><<<dim3(SEQ / 128, SEQ / 128, BATCH * NHEAD), blk, 0, 0>>>(
        SEQ, SEQ, HD, scale_base, 0.f,
        Qb, HID, (long)SEQ * HID, HD,
        Kb, HID, (long)SEQ * HID, HD,
        Sb, SEQ, (long)NHEAD * SEQ * SEQ, (long)SEQ * SEQ,
        NHEAD, 1, 0);
    causal_softmax_k<<<BATCH * NHEAD * SEQ, 256, 0, 0>>>(Sb, SEQ, SEQ);

    // stream0: AV (needs V)
    cudaStreamWaitEvent(0, g_ss.ev2, 0);
    gemm_mma<false><<<dim3(1, SEQ / 128, BATCH * NHEAD), blk, 0, 0>>>(
        SEQ, HD, SEQ, 1.f, 0.f,
        Sb, SEQ, (long)NHEAD * SEQ * SEQ, (long)SEQ * SEQ,
        Vb, HID, (long)SEQ * HID, HD,
        Ab, HID, (long)SEQ * HID, HD,
        NHEAD, 0, 1);

    // stream0: out = attn_out @ Wo^T
    gemm_mma<true><<<dim3(HID / 128, MS / 128, 1), blk, 0, 0>>>(MS, HID, HID,
        1.f, 0.f, Ab, HID, 0, 0, Wo, HID, 0, 0, out, HID, 0, 0, 1, 0, 0);

    // join: out += R * (t2 @ v_out^T)
    cudaStreamWaitEvent(0, g_ss.ev3, 0);
    gemm_mma<true><<<dim3(HID / 128, MS / 128, 1), blk, 0, 0>>>(MS, HID, RNK,
        (float)RNK, 1.f,
        t2, RNK, 0, 0, v_out, RNK, 0, 0, out, HID, 0, 0, 1, 0, 0);
}